// round 12
// baseline (speedup 1.0000x reference)
#include <cuda_runtime.h>
#include <cuda_bf16.h>
#include <math.h>
#include <stdint.h>

// ---------------- dims ----------------
static constexpr int B_ = 256, M_ = 321, P_ = 192;
static constexpr size_t FU = (size_t)B_ * M_; // 82176

// padded K dims (multiples of 16)
static constexpr int KP1 = 1616;   // 1605
static constexpr int KP2 = 976;    // 963
static constexpr int KPS = 1936;   // 1926
static constexpr int KPG = 128;    // 128

// plane sizes in floats (uint16 count / 2)
static constexpr size_t W1PL = (size_t)28*384*KP1/2;
static constexpr size_t W2PL = (size_t)28*384*KP2/2;
static constexpr size_t WSPL = (size_t)128*KPS/2;
static constexpr size_t WGPL = (size_t)384*KPG/2;

// ---------------- scratch pool offsets (in 4-byte elems) ----------------
static constexpr size_t O_Z0   = 0;                        // 192*FU
static constexpr size_t O_XR   = O_Z0   + 192*FU;          // 192*FU
static constexpr size_t O_EU0  = O_XR   + 192*FU;          // 96*FU
static constexpr size_t O_OU0  = O_EU0  +  96*FU;
static constexpr size_t O_EU1A = O_OU0  +  96*FU;          // 48*FU
static constexpr size_t O_OU1A = O_EU1A +  48*FU;
static constexpr size_t O_EU1B = O_OU1A +  48*FU;
static constexpr size_t O_OU1B = O_EU1B +  48*FU;
static constexpr size_t O_EU2  = O_OU1B +  48*FU;          // 4 x 24*FU
static constexpr size_t O_OU2  = O_EU2  + (size_t)4*24*FU; // 4 x 24*FU
static constexpr size_t O_R1   = O_OU2  + (size_t)4*24*FU; // 96*FU
static constexpr size_t O_R4   = O_R1   +  96*FU;
static constexpr size_t O_R2   = O_R4   +  96*FU;          // 48*FU
static constexpr size_t O_R3   = O_R2   +  48*FU;
static constexpr size_t O_DQ   = O_R3   +  48*FU;          // 4 x 98*FU
static constexpr size_t O_CQ   = O_DQ   + (size_t)4*98*FU;
static constexpr size_t O_YA   = O_CQ   + (size_t)4*98*FU;
static constexpr size_t O_YB   = O_YA   + (size_t)4*98*FU;
static constexpr size_t O_CC   = O_YB   + (size_t)4*98*FU; // 256*128*187
static constexpr size_t O_GI   = O_CC   + (size_t)B_*128*187;
static constexpr size_t O_H1   = O_GI   + (size_t)47872*384;
static constexpr size_t O_HS   = O_H1   + (size_t)B_*128;
static constexpr size_t O_W1H  = O_HS   + (size_t)6144*8;
static constexpr size_t O_W1L  = O_W1H  + W1PL;
static constexpr size_t O_W2H  = O_W1L  + W1PL;
static constexpr size_t O_W2L  = O_W2H  + W2PL;
static constexpr size_t O_WSH  = O_W2L  + W2PL;
static constexpr size_t O_WSL  = O_WSH  + WSPL;
static constexpr size_t O_WGH  = O_WSL  + WSPL;
static constexpr size_t O_WGL  = O_WGH  + WGPL;
static constexpr size_t POOLN  = O_WGL  + WGPL + 64;

__device__ __align__(16) float g_pool[POOLN];

// ---------------- split-bf16 packing: u32 = hi | lo<<16 ----------------
__device__ __forceinline__ uint32_t pack2(float v) {
    __nv_bfloat16 h = __float2bfloat16(v);
    float hf = __bfloat162float(h);
    __nv_bfloat16 l = __float2bfloat16(v - hf);
    return (uint32_t)__bfloat16_as_ushort(h) |
           ((uint32_t)__bfloat16_as_ushort(l) << 16);
}

// mma.sync m16n8k16 bf16, fp32 accumulate
__device__ __forceinline__ void mma16816(float* c, const uint32_t* a, const uint32_t* b) {
    asm volatile(
        "mma.sync.aligned.m16n8k16.row.col.f32.bf16.bf16.f32 "
        "{%0,%1,%2,%3}, {%4,%5,%6,%7}, {%8,%9}, {%0,%1,%2,%3};"
        : "+f"(c[0]), "+f"(c[1]), "+f"(c[2]), "+f"(c[3])
        : "r"(a[0]), "r"(a[1]), "r"(a[2]), "r"(a[3]), "r"(b[0]), "r"(b[1]));
}

__device__ __forceinline__ void ldsm_x4(uint32_t* r, uint32_t saddr) {
    asm volatile("ldmatrix.sync.aligned.m8n8.x4.shared.b16 {%0,%1,%2,%3}, [%4];"
        : "=r"(r[0]), "=r"(r[1]), "=r"(r[2]), "=r"(r[3]) : "r"(saddr));
}
__device__ __forceinline__ void ldsm_x2t(uint32_t* r, uint32_t saddr) {
    asm volatile("ldmatrix.sync.aligned.m8n8.x2.trans.shared.b16 {%0,%1}, [%2];"
        : "=r"(r[0]), "=r"(r[1]) : "r"(saddr));
}
__device__ __forceinline__ void cpa16(uint32_t sdst, const void* gsrc) {
    asm volatile("cp.async.ca.shared.global [%0], [%1], 16;"
        :: "r"(sdst), "l"(gsrc) : "memory");
}
#define CPA_COMMIT() asm volatile("cp.async.commit_group;" ::: "memory")
#define CPA_WAIT0()  asm volatile("cp.async.wait_group 0;" ::: "memory")

// ---------------- elementwise kernels ----------------
__global__ void k_transpose_x(const float* __restrict__ x, float* __restrict__ z)
{
    size_t n = FU * 192;
    for (size_t i = (size_t)blockIdx.x * blockDim.x + threadIdx.x; i < n;
         i += (size_t)gridDim.x * blockDim.x) {
        int t = (int)(i % 192);
        size_t u = i / 192;
        int m = (int)(u % 321);
        int b = (int)(u / 321);
        z[i] = x[((size_t)b * 192 + t) * 321 + m];
    }
}

__global__ void k_xr(const float* __restrict__ x, const float* __restrict__ r,
                     float* __restrict__ xr)
{
    size_t n = FU * 192;
    for (size_t i = (size_t)blockIdx.x * blockDim.x + threadIdx.x; i < n;
         i += (size_t)gridDim.x * blockDim.x) {
        int t = (int)(i % 192);
        size_t u = i / 192;
        int m = (int)(u % 321);
        int b = (int)(u / 321);
        xr[i] = x[((size_t)b * 192 + t) * 321 + m] + r[i];
    }
}

__global__ void k_zip(const float* __restrict__ a, const float* __restrict__ b,
                      float* __restrict__ o, int Th)
{
    size_t n = FU * (size_t)Th;
    for (size_t i = (size_t)blockIdx.x * blockDim.x + threadIdx.x; i < n;
         i += (size_t)gridDim.x * blockDim.x) {
        int t = (int)(i % Th);
        size_t u = i / Th;
        float* orow = o + u * (size_t)(2 * Th);
        orow[2 * t]     = a[i];
        orow[2 * t + 1] = b[i];
    }
}

// weights -> two bf16 planes (hi, lo), zero-padded to (rowsPad, Kpad)
__global__ void k_cvt_w(const float* __restrict__ w,
                        uint16_t* __restrict__ hi, uint16_t* __restrict__ lo,
                        int nconv, int rows, int rowsPad, int Kdim, int Kpad)
{
    size_t n = (size_t)nconv * rowsPad * Kpad;
    for (size_t i = (size_t)blockIdx.x * blockDim.x + threadIdx.x; i < n;
         i += (size_t)gridDim.x * blockDim.x) {
        size_t per = (size_t)rowsPad * Kpad;
        int c = (int)(i / per);
        size_t rem = i - (size_t)c * per;
        int row = (int)(rem / Kpad);
        int r = (int)(rem - (size_t)row * Kpad);
        float v = (row < rows && r < Kdim)
                ? w[((size_t)c * rows + row) * Kdim + r] : 0.f;
        __nv_bfloat16 h = __float2bfloat16(v);
        float hf = __bfloat162float(h);
        __nv_bfloat16 l = __float2bfloat16(v - hf);
        hi[i] = __bfloat16_as_ushort(h);
        lo[i] = __bfloat16_as_ushort(l);
    }
}

// ================= HMMA split-bf16 implicit-GEMM conv =================
struct ZP {
    const uint16_t* Ah; const uint16_t* Al; const float* B;
    const float* bias; const float* s1;
    float* out; int qB; int qS; int mode;
};
struct GA {
    ZP z[8];
    int Mrows, Kdim, Kpad, Cin, Tout;
    int LB, sB, pad, TmaxB;
    int L1, s1s;
    int MoutLd;
};

static constexpr int ASTR = 20;   // A row stride u32 (8 hi + 8 lo + 4 pad)
static constexpr int BSTR = 68;   // B row stride u32 (64 data + 4 pad)
static constexpr int ASTAGE = 128 * ASTR;   // u32
static constexpr int BARR = 16 * BSTR;      // u32 per array

template<int D, bool SWAP>
__global__ __launch_bounds__(256, 2) void k_mma(GA ga)
{
    __shared__ uint32_t smA[2][ASTAGE];        // [stage][row*ASTR + part*8 + kpair]
    __shared__ uint32_t smB[2][2][BARR];       // [stage][hi/lo][k*BSTR + colpair]

    const ZP zp = ga.z[blockIdx.z];
    const int tid = threadIdx.x;
    const int lane = tid & 31;
    const int wid = tid >> 5;
    const int wm = wid & 1;          // 0..1  (M warps)
    const int wn = wid >> 1;         // 0..3  (N warps)
    const int g = lane >> 2;         // 0..7
    const int t4 = lane & 3;         // 0..3
    const int colBase = blockIdx.x * 128;
    const int rowBase = blockIdx.y * 128;
    const int Mrows = ga.Mrows;

    const int Kpad = ga.Kpad, Kd = ga.Kdim;
    const int LB = ga.LB, sB = ga.sB, Tmax = ga.TmaxB;

    // ---- smem shared-space bases ----
    const uint32_t aBase = (uint32_t)__cvta_generic_to_shared(&smA[0][0]);
    const uint32_t bBase = (uint32_t)__cvta_generic_to_shared(&smB[0][0][0]);

    // ---- A fill: cp.async, thread = (row=tid>>1, half=tid&1) ----
    const int arow = tid >> 1;
    const int ahalf = tid & 1;
    const uint16_t* AH = zp.Ah + (size_t)(rowBase + arow) * Kpad + 8 * ahalf;
    const uint16_t* AL = zp.Al + (size_t)(rowBase + arow) * Kpad + 8 * ahalf;
    const uint32_t aDstHi = aBase + (uint32_t)((arow * ASTR + 4 * ahalf) * 4);
    const uint32_t aDstLo = aDstHi + 32;

    // ---- B fill addressing: thread = (kg, cp); cols 2cp, 2cp+1 ----
    const int kg = tid >> 6;                  // 0..3 -> k rows 4kg..4kg+3
    const int cp = tid & 63;                  // col pair
    const float* Bb[2];
    int tb[2];
#pragma unroll
    for (int c = 0; c < 2; c++) {
        int col = colBase + 2 * cp + c;
        int bb = col / ga.Tout;
        int t  = col - bb * ga.Tout;
        Bb[c] = zp.B + (size_t)bb * ga.Cin * LB + zp.qB;
        tb[c] = t - ga.pad;
    }

    float acc[4][4][4];
#pragma unroll
    for (int i = 0; i < 4; i++)
#pragma unroll
        for (int j = 0; j < 4; j++)
#pragma unroll
            for (int q = 0; q < 4; q++) acc[i][j][q] = 0.f;

    float bv[2][4];

    auto cpasyncA = [&](int kt, int s) {
        const uint32_t so = (uint32_t)(s * ASTAGE * 4);
        cpa16(aDstHi + so, AH + ((size_t)kt << 4));
        cpa16(aDstLo + so, AL + ((size_t)kt << 4));
    };
    auto fetchB = [&](int kt) {
        const int kg16 = kt << 4;
#pragma unroll
        for (int c = 0; c < 2; c++) {
#pragma unroll
            for (int kk = 0; kk < 4; kk++) {
                int r = kg16 + kg * 4 + kk;
                float v = 0.f;
                if (r < Kd) {
                    int cin, off;
                    if (SWAP) { cin = r % D; off = r / D; }
                    else      { cin = r / D; off = r % D; }
                    int tc = tb[c] + off;
                    tc = tc < 0 ? 0 : (tc > Tmax ? Tmax : tc);
                    v = Bb[c][(size_t)cin * LB + sB * tc];
                }
                bv[c][kk] = v;
            }
        }
    };
    auto storeB = [&](int s) {
#pragma unroll
        for (int kk = 0; kk < 4; kk++) {
            uint32_t p0 = pack2(bv[0][kk]);
            uint32_t p1 = pack2(bv[1][kk]);
            int idx = (4 * kg + kk) * BSTR + cp;
            smB[s][0][idx] = __byte_perm(p0, p1, 0x5410);
            smB[s][1][idx] = __byte_perm(p0, p1, 0x7632);
        }
    };

    // ---- ldmatrix per-thread addresses ----
    const int r16 = lane & 15;
    const uint32_t aRowOff = (uint32_t)(r16 * ASTR * 4) + ((lane >> 4) << 4);
    const uint32_t bRowOff = (uint32_t)(r16 * BSTR * 4) + (uint32_t)((32 * wn) * 2);

    const int nCh = Kpad >> 4;

    // prologue
    cpasyncA(0, 0); CPA_COMMIT();
    fetchB(0);
    storeB(0);
    CPA_WAIT0();
    __syncthreads();

    for (int kt = 0; kt < nCh; kt++) {
        const int s = kt & 1;
        const bool more = (kt + 1) < nCh;
        if (more) { cpasyncA(kt + 1, s ^ 1); CPA_COMMIT(); }
        if (more) fetchB(kt + 1);

        const uint32_t aS = aBase + (uint32_t)(s * ASTAGE * 4) + aRowOff;
        const uint32_t bHiS = bBase + (uint32_t)((s * 2) * BARR * 4) + bRowOff;
        const uint32_t bLoS = bHiS + (uint32_t)(BARR * 4);

        uint32_t bh[4][2], bl[4][2];
#pragma unroll
        for (int j = 0; j < 4; j++) {
            ldsm_x2t(bh[j], bHiS + j * 16);
            ldsm_x2t(bl[j], bLoS + j * 16);
        }
#pragma unroll
        for (int i = 0; i < 4; i++) {
            uint32_t ah[4], al[4];
            uint32_t ai = aS + (uint32_t)((64 * wm + 16 * i) * ASTR * 4);
            ldsm_x4(ah, ai);
            ldsm_x4(al, ai + 32);
#pragma unroll
            for (int j = 0; j < 4; j++) {
                mma16816(acc[i][j], ah, bh[j]);
                mma16816(acc[i][j], ah, bl[j]);
                mma16816(acc[i][j], al, bh[j]);
            }
        }
        if (more) storeB(s ^ 1);
        if (more) CPA_WAIT0();
        __syncthreads();
    }

    // ---- epilogue ----
    const int mode = zp.mode;
#pragma unroll
    for (int i = 0; i < 4; i++) {
        int row0 = rowBase + 64 * wm + 16 * i + g;
#pragma unroll
        for (int rr = 0; rr < 2; rr++) {
            int row = row0 + 8 * rr;
            if (row >= Mrows) continue;
            float bvs = zp.bias[row];
#pragma unroll
            for (int j = 0; j < 4; j++) {
#pragma unroll
                for (int cc = 0; cc < 2; cc++) {
                    int col = colBase + 32 * wn + 8 * j + 2 * t4 + cc;
                    float v = acc[i][j][rr * 2 + cc] + bvs;
                    if (mode == 5) {
                        zp.out[(size_t)col * ga.MoutLd + row] = v;
                        continue;
                    }
                    int bb = col / ga.Tout;
                    int t  = col - bb * ga.Tout;
                    size_t oi = ((size_t)bb * ga.MoutLd + row) * ga.Tout + t;
                    if (mode == 0)      v = v > 0.f ? v : 0.01f * v;
                    else if (mode == 4) v = fmaxf(v, 0.f);
                    else {
                        float s1v = zp.s1[((size_t)bb * 321 + row) * ga.L1
                                          + ga.s1s * t + zp.qS];
                        if (mode == 1)      v = s1v * expf(tanhf(v));
                        else if (mode == 2) v = s1v + tanhf(v);
                        else                v = s1v - tanhf(v);
                    }
                    zp.out[oi] = v;
                }
            }
        }
    }
}

// ---------------- GRU1: persistent recurrence ----------------
__global__ __launch_bounds__(384, 1) void k_gru1(
    const float* __restrict__ GI, const float* __restrict__ whh,
    const float* __restrict__ bhh, float* __restrict__ H1)
{
    __shared__ __align__(16) float hs[2][128];
    __shared__ float gs[2][384];
    const int tid = threadIdx.x;
    const int b0 = blockIdx.x * 2;

    float w[128];
#pragma unroll
    for (int k = 0; k < 128; k++) w[k] = whh[(size_t)tid * 128 + k];
    const float bh = bhh[tid];

    if (tid < 128) { hs[0][tid] = 0.f; hs[1][tid] = 0.f; }
    __syncthreads();

    for (int t = 0; t < 187; t++) {
        float g0 = bh, g1 = bh;
#pragma unroll
        for (int k4 = 0; k4 < 32; k4++) {
            float4 h0 = *(const float4*)&hs[0][k4 * 4];
            float4 h1 = *(const float4*)&hs[1][k4 * 4];
            g0 = fmaf(w[k4*4+0], h0.x, g0); g1 = fmaf(w[k4*4+0], h1.x, g1);
            g0 = fmaf(w[k4*4+1], h0.y, g0); g1 = fmaf(w[k4*4+1], h1.y, g1);
            g0 = fmaf(w[k4*4+2], h0.z, g0); g1 = fmaf(w[k4*4+2], h1.z, g1);
            g0 = fmaf(w[k4*4+3], h0.w, g0); g1 = fmaf(w[k4*4+3], h1.w, g1);
        }
        gs[0][tid] = g0;
        gs[1][tid] = g1;
        __syncthreads();

        float hnew = 0.f;
        int bb = 0, j = 0;
        if (tid < 256) {
            bb = tid >> 7; j = tid & 127;
            size_t base = ((size_t)(b0 + bb) * 187 + t) * 384;
            float ir = GI[base + j], iz = GI[base + 128 + j], inn = GI[base + 256 + j];
            float hr = gs[bb][j], hz = gs[bb][128 + j], hn = gs[bb][256 + j];
            float rg = 1.f / (1.f + expf(-(ir + hr)));
            float zg = 1.f / (1.f + expf(-(iz + hz)));
            float ng = tanhf(inn + rg * hn);
            hnew = (1.f - zg) * ng + zg * hs[bb][j];
        }
        __syncthreads();
        if (tid < 256) hs[bb][j] = hnew;
        __syncthreads();
    }
    if (tid < 256) H1[(size_t)(b0 + (tid >> 7)) * 128 + (tid & 127)] = hs[tid >> 7][tid & 127];
}

// ---------------- skip GRU ----------------
__global__ __launch_bounds__(128) void k_skipgru(
    const float* __restrict__ C, const float* __restrict__ wih,
    const float* __restrict__ whh, const float* __restrict__ bih,
    const float* __restrict__ bhh, float* __restrict__ HS)
{
    __shared__ float wi[24 * 128];
    __shared__ float wh[24 * 8];
    __shared__ float bi[24], bh[24];
    const int tid = threadIdx.x;
    for (int i = tid; i < 24 * 128; i += 128) wi[i] = wih[i];
    for (int i = tid; i < 24 * 8; i += 128) wh[i] = whh[i];
    if (tid < 24) { bi[tid] = bih[tid]; bh[tid] = bhh[tid]; }
    __syncthreads();

    const int n = blockIdx.x * 128 + tid;
    const int b = n / 24, sk = n - b * 24;
    float h[8];
#pragma unroll
    for (int u = 0; u < 8; u++) h[u] = 0.f;

    for (int pt = 0; pt < 7; pt++) {
        int l = 19 + pt * 24 + sk;
        float gi[24];
#pragma unroll
        for (int g = 0; g < 24; g++) gi[g] = bi[g];
        for (int ch = 0; ch < 128; ch++) {
            float xv = C[((size_t)b * 128 + ch) * 187 + l];
#pragma unroll
            for (int g = 0; g < 24; g++) gi[g] = fmaf(wi[g * 128 + ch], xv, gi[g]);
        }
        float gh[24];
#pragma unroll
        for (int g = 0; g < 24; g++) {
            float a = bh[g];
#pragma unroll
            for (int u = 0; u < 8; u++) a = fmaf(wh[g * 8 + u], h[u], a);
            gh[g] = a;
        }
#pragma unroll
        for (int u = 0; u < 8; u++) {
            float rg = 1.f / (1.f + expf(-(gi[u] + gh[u])));
            float zg = 1.f / (1.f + expf(-(gi[8 + u] + gh[8 + u])));
            float ng = tanhf(gi[16 + u] + rg * gh[16 + u]);
            h[u] = (1.f - zg) * ng + zg * h[u];
        }
    }
#pragma unroll
    for (int u = 0; u < 8; u++) HS[(size_t)n * 8 + u] = h[u];
}

// ---------------- head ----------------
__global__ void k_final(const float* __restrict__ H1, const float* __restrict__ HS,
                        const float* __restrict__ lin_w, const float* __restrict__ lin_b,
                        const float* __restrict__ hw_w, const float* __restrict__ hw_b,
                        const float* __restrict__ XR, float* __restrict__ out)
{
    int id = blockIdx.x * blockDim.x + threadIdx.x;
    if (id >= 82176) return;
    int b = id / 321, m = id - b * 321;
    const float* wr = lin_w + (size_t)m * 320;
    float acc = lin_b[m];
    const float* h1 = H1 + (size_t)b * 128;
    for (int j = 0; j < 128; j++) acc = fmaf(wr[j], h1[j], acc);
    const float* hsv = HS + (size_t)b * 192;
    for (int q = 0; q < 192; q++) acc = fmaf(wr[128 + q], hsv[q], acc);
    float z = hw_b[0];
    const float* xr = XR + (size_t)id * 192 + 168;
    for (int k = 0; k < 24; k++) z = fmaf(hw_w[k], xr[k], z);
    out[id] = acc + z;
}

// ---------------- host driver ----------------
struct NodeIO { int wi; const float* Z; float* EU; float* OU; };

static void run_nodes(const float* b1, const float* b2, float* pool,
                      const NodeIO* nd, int cnt, int Th)
{
    const uint16_t* W1h = (const uint16_t*)(pool + O_W1H);
    const uint16_t* W1l = (const uint16_t*)(pool + O_W1L);
    const uint16_t* W2h = (const uint16_t*)(pool + O_W2H);
    const uint16_t* W2l = (const uint16_t*)(pool + O_W2L);
    auto W1H = [&](int wi, int j){ return W1h + (size_t)(wi * 4 + j) * 384 * KP1; };
    auto W1L = [&](int wi, int j){ return W1l + (size_t)(wi * 4 + j) * 384 * KP1; };
    auto W2H = [&](int wi, int j){ return W2h + (size_t)(wi * 4 + j) * 384 * KP2; };
    auto W2L = [&](int wi, int j){ return W2l + (size_t)(wi * 4 + j) * 384 * KP2; };
    auto B1 = [&](int wi, int j){ return b1 + (size_t)(wi * 4 + j) * 321; };
    auto B2 = [&](int wi, int j){ return b2 + (size_t)(wi * 4 + j) * 321; };

    float* DQ[4]; float* CQ[4]; float* YA[4]; float* YB[4];
    for (int n = 0; n < 4; n++) {
        DQ[n] = pool + O_DQ + (size_t)n * 98 * FU;
        CQ[n] = pool + O_CQ + (size_t)n * 98 * FU;
        YA[n] = pool + O_YA + (size_t)n * 98 * FU;
        YB[n] = pool + O_YB + (size_t)n * 98 * FU;
    }

    dim3 g1((256 * (Th + 2)) / 128, 3, 2 * cnt);
    dim3 g2((256 * Th) / 128, 3, 2 * cnt);

    // conv1 phi/psi: B = strided e/o view of Z (fp32), replication pad 3
    {
        GA a{};
        for (int n = 0; n < cnt; n++) {
            a.z[2*n]   = {W1H(nd[n].wi, 0), W1L(nd[n].wi, 0), nd[n].Z, B1(nd[n].wi, 0), nullptr, YA[n], 0, 0, 0};
            a.z[2*n+1] = {W1H(nd[n].wi, 1), W1L(nd[n].wi, 1), nd[n].Z, B1(nd[n].wi, 1), nullptr, YB[n], 1, 0, 0};
        }
        a.Mrows = 321; a.Kdim = 1605; a.Kpad = KP1; a.Cin = 321; a.Tout = Th + 2;
        a.LB = 2 * Th; a.sB = 2; a.pad = 3; a.TmaxB = Th - 1;
        a.L1 = 0; a.s1s = 0; a.MoutLd = 321;
        k_mma<5, false><<<g1, 256>>>(a);
    }
    // conv2 phi/psi: mode 1, src1 = o/e strided views of Z
    {
        GA a{};
        for (int n = 0; n < cnt; n++) {
            a.z[2*n]   = {W2H(nd[n].wi, 0), W2L(nd[n].wi, 0), YA[n], B2(nd[n].wi, 0), nd[n].Z, DQ[n], 0, 1, 1};
            a.z[2*n+1] = {W2H(nd[n].wi, 1), W2L(nd[n].wi, 1), YB[n], B2(nd[n].wi, 1), nd[n].Z, CQ[n], 0, 0, 1};
        }
        a.Mrows = 321; a.Kdim = 963; a.Kpad = KP2; a.Cin = 321; a.Tout = Th;
        a.LB = Th + 2; a.sB = 1; a.pad = 0; a.TmaxB = Th + 1;
        a.L1 = 2 * Th; a.s1s = 2; a.MoutLd = 321;
        k_mma<3, false><<<g2, 256>>>(a);
    }
    // conv1 U/P: B = D/C dense, pad 3
    {
        GA a{};
        for (int n = 0; n < cnt; n++) {
            a.z[2*n]   = {W1H(nd[n].wi, 2), W1L(nd[n].wi, 2), DQ[n], B1(nd[n].wi, 2), nullptr, YA[n], 0, 0, 0};
            a.z[2*n+1] = {W1H(nd[n].wi, 3), W1L(nd[n].wi, 3), CQ[n], B1(nd[n].wi, 3), nullptr, YB[n], 0, 0, 0};
        }
        a.Mrows = 321; a.Kdim = 1605; a.Kpad = KP1; a.Cin = 321; a.Tout = Th + 2;
        a.LB = Th; a.sB = 1; a.pad = 3; a.TmaxB = Th - 1;
        a.L1 = 0; a.s1s = 0; a.MoutLd = 321;
        k_mma<5, false><<<g1, 256>>>(a);
    }
    // conv2 U/P: EU = C + tanh (mode 2), OU = D - tanh (mode 3)
    {
        GA a{};
        for (int n = 0; n < cnt; n++) {
            a.z[2*n]   = {W2H(nd[n].wi, 2), W2L(nd[n].wi, 2), YA[n], B2(nd[n].wi, 2), CQ[n], nd[n].EU, 0, 0, 2};
            a.z[2*n+1] = {W2H(nd[n].wi, 3), W2L(nd[n].wi, 3), YB[n], B2(nd[n].wi, 3), DQ[n], nd[n].OU, 0, 0, 3};
        }
        a.Mrows = 321; a.Kdim = 963; a.Kpad = KP2; a.Cin = 321; a.Tout = Th;
        a.LB = Th + 2; a.sB = 1; a.pad = 0; a.TmaxB = Th + 1;
        a.L1 = Th; a.s1s = 1; a.MoutLd = 321;
        k_mma<3, false><<<g2, 256>>>(a);
    }
}

extern "C" void kernel_launch(void* const* d_in, const int* in_sizes, int n_in,
                              void* d_out, int out_size)
{
    float* pool = nullptr;
    cudaGetSymbolAddress((void**)&pool, g_pool);

    const float* x     = (const float*)d_in[0];
    const float* tw1   = (const float*)d_in[1];
    const float* tb1   = (const float*)d_in[2];
    const float* tw2   = (const float*)d_in[3];
    const float* tb2   = (const float*)d_in[4];
    const float* c1w   = (const float*)d_in[5];
    const float* c1b   = (const float*)d_in[6];
    const float* g1wih = (const float*)d_in[7];
    const float* g1whh = (const float*)d_in[8];
    const float* g1bih = (const float*)d_in[9];
    const float* g1bhh = (const float*)d_in[10];
    const float* gswih = (const float*)d_in[11];
    const float* gswhh = (const float*)d_in[12];
    const float* gsbih = (const float*)d_in[13];
    const float* gsbhh = (const float*)d_in[14];
    const float* linw  = (const float*)d_in[15];
    const float* linb  = (const float*)d_in[16];
    const float* hww   = (const float*)d_in[17];
    const float* hwb   = (const float*)d_in[18];

    float* Z0   = pool + O_Z0;
    float* XR   = pool + O_XR;
    float* EU0  = pool + O_EU0;  float* OU0  = pool + O_OU0;
    float* EU1A = pool + O_EU1A; float* OU1A = pool + O_OU1A;
    float* EU1B = pool + O_EU1B; float* OU1B = pool + O_OU1B;
    float* EU2[4]; float* OU2[4];
    for (int n = 0; n < 4; n++) {
        EU2[n] = pool + O_EU2 + (size_t)n * 24 * FU;
        OU2[n] = pool + O_OU2 + (size_t)n * 24 * FU;
    }
    float* R1 = pool + O_R1; float* R4 = pool + O_R4;
    float* R2 = pool + O_R2; float* R3 = pool + O_R3;
    float* CC  = pool + O_CC;
    float* GIb = pool + O_GI;
    float* H1  = pool + O_H1;
    float* HS  = pool + O_HS;

    // 0) weight conversion (split bf16 hi/lo planes, padded)
    k_cvt_w<<<8192, 256>>>(tw1, (uint16_t*)(pool + O_W1H), (uint16_t*)(pool + O_W1L),
                           28, 321, 384, 1605, KP1);
    k_cvt_w<<<8192, 256>>>(tw2, (uint16_t*)(pool + O_W2H), (uint16_t*)(pool + O_W2L),
                           28, 321, 384, 963, KP2);
    k_cvt_w<<<1024, 256>>>(c1w, (uint16_t*)(pool + O_WSH), (uint16_t*)(pool + O_WSL),
                           1, 128, 128, 1926, KPS);
    k_cvt_w<<<192, 256>>>(g1wih, (uint16_t*)(pool + O_WGH), (uint16_t*)(pool + O_WGL),
                          1, 384, 384, 128, KPG);

    // 1) x -> BMT layout
    k_transpose_x<<<1024, 256>>>(x, Z0);

    // 2) SCINet tree, level-batched
    NodeIO n0[1] = {{0, Z0, EU0, OU0}};
    run_nodes(tb1, tb2, pool, n0, 1, 96);
    NodeIO n1[2] = {{1, EU0, EU1A, OU1A}, {4, OU0, EU1B, OU1B}};
    run_nodes(tb1, tb2, pool, n1, 2, 48);
    NodeIO n2[4] = {{2, EU1A, EU2[0], OU2[0]}, {3, OU1A, EU2[1], OU2[1]},
                    {5, EU1B, EU2[2], OU2[2]}, {6, OU1B, EU2[3], OU2[3]}};
    run_nodes(tb1, tb2, pool, n2, 4, 24);

    // zip-up-the-pants
    k_zip<<<512, 256>>>(EU2[0], OU2[0], R2, 24);
    k_zip<<<512, 256>>>(EU2[1], OU2[1], R3, 24);
    k_zip<<<1024, 256>>>(R2, R3, R1, 48);
    k_zip<<<512, 256>>>(EU2[2], OU2[2], R2, 24);
    k_zip<<<512, 256>>>(EU2[3], OU2[3], R3, 24);
    k_zip<<<1024, 256>>>(R2, R3, R4, 48);
    k_zip<<<1024, 256>>>(R1, R4, Z0, 96);     // res1 -> Z0

    // 3) xr = x + res1
    k_xr<<<1024, 256>>>(x, Z0, XR);

    // 4) conv stage (full-width Conv2d + relu): r = k*321 + m
    {
        GA a{};
        a.z[0] = {(const uint16_t*)(pool + O_WSH), (const uint16_t*)(pool + O_WSL),
                  XR, c1b, nullptr, CC, 0, 0, 4};
        a.Mrows = 128; a.Kdim = 1926; a.Kpad = KPS; a.Cin = 321; a.Tout = 187;
        a.LB = 192; a.sB = 1; a.pad = 0; a.TmaxB = 191;
        a.L1 = 0; a.s1s = 0; a.MoutLd = 128;
        k_mma<321, true><<<dim3(374, 1, 1), 256>>>(a);
    }

    // 5) GRU1 input projection (transposed store)
    {
        GA a{};
        a.z[0] = {(const uint16_t*)(pool + O_WGH), (const uint16_t*)(pool + O_WGL),
                  CC, g1bih, nullptr, GIb, 0, 0, 5};
        a.Mrows = 384; a.Kdim = 128; a.Kpad = KPG; a.Cin = 128; a.Tout = 187;
        a.LB = 187; a.sB = 1; a.pad = 0; a.TmaxB = 186;
        a.L1 = 0; a.s1s = 0; a.MoutLd = 384;
        k_mma<1, false><<<dim3(374, 3, 1), 256>>>(a);
    }

    // 6) GRU1 recurrence
    k_gru1<<<128, 384>>>(GIb, g1whh, g1bhh, H1);

    // 7) skip GRU
    k_skipgru<<<48, 128>>>(CC, gswih, gswhh, gsbih, gsbhh, HS);

    // 8) head
    k_final<<<(82176 + 255) / 256, 256>>>(H1, HS, linw, linb, hww, hwb, XR,
                                          (float*)d_out);
}

// round 14
// speedup vs baseline: 1.0181x; 1.0181x over previous
#include <cuda_runtime.h>
#include <cuda_bf16.h>
#include <math.h>
#include <stdint.h>

// ---------------- dims ----------------
static constexpr int B_ = 256, M_ = 321, P_ = 192;
static constexpr size_t FU = (size_t)B_ * M_; // 82176

// padded K dims (multiples of 16)
static constexpr int KP1 = 1616;   // 1605
static constexpr int KP2 = 976;    // 963
static constexpr int KPS = 1936;   // 1926
static constexpr int KPG = 128;    // 128

// ---------------- scratch pool offsets (in 4-byte elems) ----------------
static constexpr size_t O_Z0   = 0;                        // 192*FU
static constexpr size_t O_XR   = O_Z0   + 192*FU;          // 192*FU
static constexpr size_t O_EU0  = O_XR   + 192*FU;          // 96*FU
static constexpr size_t O_OU0  = O_EU0  +  96*FU;
static constexpr size_t O_EU1A = O_OU0  +  96*FU;          // 48*FU
static constexpr size_t O_OU1A = O_EU1A +  48*FU;
static constexpr size_t O_EU1B = O_OU1A +  48*FU;
static constexpr size_t O_OU1B = O_EU1B +  48*FU;
static constexpr size_t O_EU2  = O_OU1B +  48*FU;          // 4 x 24*FU
static constexpr size_t O_OU2  = O_EU2  + (size_t)4*24*FU; // 4 x 24*FU
static constexpr size_t O_R1   = O_OU2  + (size_t)4*24*FU; // 96*FU
static constexpr size_t O_R4   = O_R1   +  96*FU;
static constexpr size_t O_R2   = O_R4   +  96*FU;          // 48*FU
static constexpr size_t O_R3   = O_R2   +  48*FU;
static constexpr size_t O_DQ   = O_R3   +  48*FU;          // 4 x 98*FU
static constexpr size_t O_CQ   = O_DQ   + (size_t)4*98*FU;
static constexpr size_t O_YA   = O_CQ   + (size_t)4*98*FU;
static constexpr size_t O_YB   = O_YA   + (size_t)4*98*FU;
static constexpr size_t O_CC   = O_YB   + (size_t)4*98*FU; // 256*128*187
static constexpr size_t O_GI   = O_CC   + (size_t)B_*128*187;
static constexpr size_t O_H1   = O_GI   + (size_t)47872*384;
static constexpr size_t O_HS   = O_H1   + (size_t)B_*128;
static constexpr size_t O_W1PK = O_HS   + (size_t)6144*8;      // 28*384*KP1
static constexpr size_t O_W2PK = O_W1PK + (size_t)28*384*KP1;  // 28*384*KP2
static constexpr size_t O_WSPK = O_W2PK + (size_t)28*384*KP2;  // 128*KPS
static constexpr size_t O_WGPK = O_WSPK + (size_t)128*KPS;     // 384*KPG
static constexpr size_t POOLN  = O_WGPK + (size_t)384*KPG + 64;

__device__ __align__(16) float g_pool[POOLN];

// ---------------- split-bf16 packing: u32 = hi | lo<<16 ----------------
__device__ __forceinline__ uint32_t pack2(float v) {
    __nv_bfloat16 h = __float2bfloat16(v);
    float hf = __bfloat162float(h);
    __nv_bfloat16 l = __float2bfloat16(v - hf);
    return (uint32_t)__bfloat16_as_ushort(h) |
           ((uint32_t)__bfloat16_as_ushort(l) << 16);
}

// mma.sync m16n8k16 bf16, fp32 accumulate
__device__ __forceinline__ void mma16816(float* c, const uint32_t* a, const uint32_t* b) {
    asm volatile(
        "mma.sync.aligned.m16n8k16.row.col.f32.bf16.bf16.f32 "
        "{%0,%1,%2,%3}, {%4,%5,%6,%7}, {%8,%9}, {%0,%1,%2,%3};"
        : "+f"(c[0]), "+f"(c[1]), "+f"(c[2]), "+f"(c[3])
        : "r"(a[0]), "r"(a[1]), "r"(a[2]), "r"(a[3]), "r"(b[0]), "r"(b[1]));
}

__device__ __forceinline__ void ldsm_x4(uint32_t* r, uint32_t saddr) {
    asm volatile("ldmatrix.sync.aligned.m8n8.x4.shared.b16 {%0,%1,%2,%3}, [%4];"
        : "=r"(r[0]), "=r"(r[1]), "=r"(r[2]), "=r"(r[3]) : "r"(saddr));
}
__device__ __forceinline__ void ldsm_x2t(uint32_t* r, uint32_t saddr) {
    asm volatile("ldmatrix.sync.aligned.m8n8.x2.trans.shared.b16 {%0,%1}, [%2];"
        : "=r"(r[0]), "=r"(r[1]) : "r"(saddr));
}

// ---------------- elementwise kernels ----------------
__global__ void k_transpose_x(const float* __restrict__ x, float* __restrict__ z)
{
    size_t n = FU * 192;
    for (size_t i = (size_t)blockIdx.x * blockDim.x + threadIdx.x; i < n;
         i += (size_t)gridDim.x * blockDim.x) {
        int t = (int)(i % 192);
        size_t u = i / 192;
        int m = (int)(u % 321);
        int b = (int)(u / 321);
        z[i] = x[((size_t)b * 192 + t) * 321 + m];
    }
}

__global__ void k_xr(const float* __restrict__ x, const float* __restrict__ r,
                     float* __restrict__ xr)
{
    size_t n = FU * 192;
    for (size_t i = (size_t)blockIdx.x * blockDim.x + threadIdx.x; i < n;
         i += (size_t)gridDim.x * blockDim.x) {
        int t = (int)(i % 192);
        size_t u = i / 192;
        int m = (int)(u % 321);
        int b = (int)(u / 321);
        xr[i] = x[((size_t)b * 192 + t) * 321 + m] + r[i];
    }
}

__global__ void k_zip(const float* __restrict__ a, const float* __restrict__ b,
                      float* __restrict__ o, int Th)
{
    size_t n = FU * (size_t)Th;
    for (size_t i = (size_t)blockIdx.x * blockDim.x + threadIdx.x; i < n;
         i += (size_t)gridDim.x * blockDim.x) {
        int t = (int)(i % Th);
        size_t u = i / Th;
        float* orow = o + u * (size_t)(2 * Th);
        orow[2 * t]     = a[i];
        orow[2 * t + 1] = b[i];
    }
}

// weights -> packed split-bf16, zero-padded to (rowsPad, Kpad)
__global__ void k_cvt_w(const float* __restrict__ w, uint32_t* __restrict__ o,
                        int nconv, int rows, int rowsPad, int Kdim, int Kpad)
{
    size_t n = (size_t)nconv * rowsPad * Kpad;
    for (size_t i = (size_t)blockIdx.x * blockDim.x + threadIdx.x; i < n;
         i += (size_t)gridDim.x * blockDim.x) {
        size_t per = (size_t)rowsPad * Kpad;
        int c = (int)(i / per);
        size_t rem = i - (size_t)c * per;
        int row = (int)(rem / Kpad);
        int r = (int)(rem - (size_t)row * Kpad);
        float v = (row < rows && r < Kdim)
                ? w[((size_t)c * rows + row) * Kdim + r] : 0.f;
        o[i] = pack2(v);
    }
}

// ================= HMMA split-bf16 implicit-GEMM conv (128x64 tile) ======
struct ZP {
    const uint32_t* A; const float* B; const float* bias; const float* s1;
    float* out; int qB; int qS; int mode;
};
struct GA {
    ZP z[8];
    int Mrows, Kdim, Kpad, Cin, Tout;
    int LB, sB, pad, TmaxB;
    int L1, s1s;
    int MoutLd;
};

static constexpr int ASTR = 20;   // A row stride u32 (8 hi + 8 lo + 4 pad)
static constexpr int BSTR = 36;   // B row stride u32 (32 colpairs + 4 pad)
static constexpr int ASTAGE = 128 * ASTR;   // u32
static constexpr int BARR = 16 * BSTR;      // u32 per array

template<int D, bool SWAP>
__global__ __launch_bounds__(256, 3) void k_mma(GA ga)
{
    __shared__ uint32_t smA[2][ASTAGE];        // [stage][row*ASTR + part*8 + kpair]
    __shared__ uint32_t smB[2][2][BARR];       // [stage][hi/lo][k*BSTR + colpair]

    const ZP zp = ga.z[blockIdx.z];
    const int tid = threadIdx.x;
    const int lane = tid & 31;
    const int wid = tid >> 5;
    const int wm = wid & 1;          // 0..1  (M warps)
    const int wn = wid >> 1;         // 0..3  (N warps, 16 cols each)
    const int g = lane >> 2;         // 0..7
    const int t4 = lane & 3;         // 0..3
    const int colBase = blockIdx.x * 64;
    const int rowBase = blockIdx.y * 128;
    const int Mrows = ga.Mrows;

    const int Kpad = ga.Kpad, Kd = ga.Kdim;
    const int LB = ga.LB, sB = ga.sB, Tmax = ga.TmaxB;

    // ---- A fill addressing (identical to 128-wide version) ----
    const int frow = tid >> 2;                // 0..63
    const int fk0 = (tid & 3) * 4;            // k offset 0,4,8,12
    const uint32_t* Arow0 = zp.A + (size_t)(rowBase + frow) * Kpad + fk0;
    const uint32_t* Arow1 = Arow0 + (size_t)64 * Kpad;

    // ---- B fill addressing: thread = (kg 0..7, cp 0..31); cols 2cp, 2cp+1 ----
    const int kg = tid >> 5;                  // 0..7 -> k rows 2kg..2kg+1
    const int cp = tid & 31;                  // col pair
    const float* Bb[2];
    int tb[2];
#pragma unroll
    for (int c = 0; c < 2; c++) {
        int col = colBase + 2 * cp + c;
        int bb = col / ga.Tout;
        int t  = col - bb * ga.Tout;
        Bb[c] = zp.B + (size_t)bb * ga.Cin * LB + zp.qB;
        tb[c] = t - ga.pad;
    }

    float acc[4][2][4];
#pragma unroll
    for (int i = 0; i < 4; i++)
#pragma unroll
        for (int j = 0; j < 2; j++)
#pragma unroll
            for (int q = 0; q < 4; q++) acc[i][j][q] = 0.f;

    uint4 av[2];
    float bv[2][2];

    auto fetch = [&](int kt) {
        const int kg16 = kt << 4;
        av[0] = *(const uint4*)(Arow0 + kg16);
        av[1] = *(const uint4*)(Arow1 + kg16);
#pragma unroll
        for (int c = 0; c < 2; c++) {
#pragma unroll
            for (int kk = 0; kk < 2; kk++) {
                int r = kg16 + kg * 2 + kk;
                float v = 0.f;
                if (r < Kd) {
                    int cin, off;
                    if (SWAP) { cin = r % D; off = r / D; }
                    else      { cin = r / D; off = r % D; }
                    int tc = tb[c] + off;
                    tc = tc < 0 ? 0 : (tc > Tmax ? Tmax : tc);
                    v = Bb[c][(size_t)cin * LB + sB * tc];
                }
                bv[c][kk] = v;
            }
        }
    };
    auto store = [&](int s) {
        const int kq = fk0 >> 1;
        // A: rows frow, frow+64 ; packed u32 -> hi plane + lo plane
#pragma unroll
        for (int p = 0; p < 2; p++) {
            uint4 v = (p == 0) ? av[0] : av[1];
            int base = (frow + 64 * p) * ASTR + kq;
            *(uint2*)&smA[s][base] =
                make_uint2(__byte_perm(v.x, v.y, 0x5410), __byte_perm(v.z, v.w, 0x5410));
            *(uint2*)&smA[s][base + 8] =
                make_uint2(__byte_perm(v.x, v.y, 0x7632), __byte_perm(v.z, v.w, 0x7632));
        }
        // B: k rows 2kg..2kg+1, col pair cp
#pragma unroll
        for (int kk = 0; kk < 2; kk++) {
            uint32_t p0 = pack2(bv[0][kk]);
            uint32_t p1 = pack2(bv[1][kk]);
            int idx = (2 * kg + kk) * BSTR + cp;
            smB[s][0][idx] = __byte_perm(p0, p1, 0x5410);
            smB[s][1][idx] = __byte_perm(p0, p1, 0x7632);
        }
    };

    // ---- ldmatrix per-thread addresses ----
    uint32_t aBase = (uint32_t)__cvta_generic_to_shared(&smA[0][0]);
    uint32_t bBase = (uint32_t)__cvta_generic_to_shared(&smB[0][0][0]);
    const int r16 = lane & 15;
    const uint32_t aRowOff = (uint32_t)(r16 * ASTR * 4) + ((lane >> 4) << 4);
    const uint32_t bRowOff = (uint32_t)(r16 * BSTR * 4) + (uint32_t)((16 * wn) * 2);

    const int nCh = Kpad >> 4;

    fetch(0);
    store(0);
    __syncthreads();
    for (int kt = 0; kt < nCh; kt++) {
        if (kt + 1 < nCh) fetch(kt + 1);

        const int s = kt & 1;
        const uint32_t aS = aBase + (uint32_t)(s * ASTAGE * 4) + aRowOff;
        const uint32_t bHiS = bBase + (uint32_t)((s * 2) * BARR * 4) + bRowOff;
        const uint32_t bLoS = bHiS + (uint32_t)(BARR * 4);

        uint32_t bh[2][2], bl[2][2];
#pragma unroll
        for (int j = 0; j < 2; j++) {
            ldsm_x2t(bh[j], bHiS + j * 16);
            ldsm_x2t(bl[j], bLoS + j * 16);
        }
#pragma unroll
        for (int i = 0; i < 4; i++) {
            uint32_t ah[4], al[4];
            uint32_t ai = aS + (uint32_t)((64 * wm + 16 * i) * ASTR * 4);
            ldsm_x4(ah, ai);
            ldsm_x4(al, ai + 32);
#pragma unroll
            for (int j = 0; j < 2; j++) {
                mma16816(acc[i][j], ah, bh[j]);
                mma16816(acc[i][j], ah, bl[j]);
                mma16816(acc[i][j], al, bh[j]);
            }
        }
        if (kt + 1 < nCh) store((kt + 1) & 1);
        __syncthreads();
    }

    // ---- epilogue ----
    const int mode = zp.mode;
#pragma unroll
    for (int i = 0; i < 4; i++) {
        int row0 = rowBase + 64 * wm + 16 * i + g;
#pragma unroll
        for (int rr = 0; rr < 2; rr++) {
            int row = row0 + 8 * rr;
            if (row >= Mrows) continue;
            float bvs = zp.bias[row];
#pragma unroll
            for (int j = 0; j < 2; j++) {
#pragma unroll
                for (int cc = 0; cc < 2; cc++) {
                    int col = colBase + 16 * wn + 8 * j + 2 * t4 + cc;
                    float v = acc[i][j][rr * 2 + cc] + bvs;
                    if (mode == 5) {
                        zp.out[(size_t)col * ga.MoutLd + row] = v;
                        continue;
                    }
                    int bb = col / ga.Tout;
                    int t  = col - bb * ga.Tout;
                    size_t oi = ((size_t)bb * ga.MoutLd + row) * ga.Tout + t;
                    if (mode == 0)      v = v > 0.f ? v : 0.01f * v;
                    else if (mode == 4) v = fmaxf(v, 0.f);
                    else {
                        float s1v = zp.s1[((size_t)bb * 321 + row) * ga.L1
                                          + ga.s1s * t + zp.qS];
                        if (mode == 1)      v = s1v * expf(tanhf(v));
                        else if (mode == 2) v = s1v + tanhf(v);
                        else                v = s1v - tanhf(v);
                    }
                    zp.out[oi] = v;
                }
            }
        }
    }
}

// ---------------- GRU1: persistent recurrence ----------------
__global__ __launch_bounds__(384, 1) void k_gru1(
    const float* __restrict__ GI, const float* __restrict__ whh,
    const float* __restrict__ bhh, float* __restrict__ H1)
{
    __shared__ __align__(16) float hs[2][128];
    __shared__ float gs[2][384];
    const int tid = threadIdx.x;
    const int b0 = blockIdx.x * 2;

    float w[128];
#pragma unroll
    for (int k = 0; k < 128; k++) w[k] = whh[(size_t)tid * 128 + k];
    const float bh = bhh[tid];

    if (tid < 128) { hs[0][tid] = 0.f; hs[1][tid] = 0.f; }
    __syncthreads();

    for (int t = 0; t < 187; t++) {
        float g0 = bh, g1 = bh;
#pragma unroll
        for (int k4 = 0; k4 < 32; k4++) {
            float4 h0 = *(const float4*)&hs[0][k4 * 4];
            float4 h1 = *(const float4*)&hs[1][k4 * 4];
            g0 = fmaf(w[k4*4+0], h0.x, g0); g1 = fmaf(w[k4*4+0], h1.x, g1);
            g0 = fmaf(w[k4*4+1], h0.y, g0); g1 = fmaf(w[k4*4+1], h1.y, g1);
            g0 = fmaf(w[k4*4+2], h0.z, g0); g1 = fmaf(w[k4*4+2], h1.z, g1);
            g0 = fmaf(w[k4*4+3], h0.w, g0); g1 = fmaf(w[k4*4+3], h1.w, g1);
        }
        gs[0][tid] = g0;
        gs[1][tid] = g1;
        __syncthreads();

        float hnew = 0.f;
        int bb = 0, j = 0;
        if (tid < 256) {
            bb = tid >> 7; j = tid & 127;
            size_t base = ((size_t)(b0 + bb) * 187 + t) * 384;
            float ir = GI[base + j], iz = GI[base + 128 + j], inn = GI[base + 256 + j];
            float hr = gs[bb][j], hz = gs[bb][128 + j], hn = gs[bb][256 + j];
            float rg = 1.f / (1.f + expf(-(ir + hr)));
            float zg = 1.f / (1.f + expf(-(iz + hz)));
            float ng = tanhf(inn + rg * hn);
            hnew = (1.f - zg) * ng + zg * hs[bb][j];
        }
        __syncthreads();
        if (tid < 256) hs[bb][j] = hnew;
        __syncthreads();
    }
    if (tid < 256) H1[(size_t)(b0 + (tid >> 7)) * 128 + (tid & 127)] = hs[tid >> 7][tid & 127];
}

// ---------------- skip GRU ----------------
__global__ __launch_bounds__(128) void k_skipgru(
    const float* __restrict__ C, const float* __restrict__ wih,
    const float* __restrict__ whh, const float* __restrict__ bih,
    const float* __restrict__ bhh, float* __restrict__ HS)
{
    __shared__ float wi[24 * 128];
    __shared__ float wh[24 * 8];
    __shared__ float bi[24], bh[24];
    const int tid = threadIdx.x;
    for (int i = tid; i < 24 * 128; i += 128) wi[i] = wih[i];
    for (int i = tid; i < 24 * 8; i += 128) wh[i] = whh[i];
    if (tid < 24) { bi[tid] = bih[tid]; bh[tid] = bhh[tid]; }
    __syncthreads();

    const int n = blockIdx.x * 128 + tid;
    const int b = n / 24, sk = n - b * 24;
    float h[8];
#pragma unroll
    for (int u = 0; u < 8; u++) h[u] = 0.f;

    for (int pt = 0; pt < 7; pt++) {
        int l = 19 + pt * 24 + sk;
        float gi[24];
#pragma unroll
        for (int g = 0; g < 24; g++) gi[g] = bi[g];
        for (int ch = 0; ch < 128; ch++) {
            float xv = C[((size_t)b * 128 + ch) * 187 + l];
#pragma unroll
            for (int g = 0; g < 24; g++) gi[g] = fmaf(wi[g * 128 + ch], xv, gi[g]);
        }
        float gh[24];
#pragma unroll
        for (int g = 0; g < 24; g++) {
            float a = bh[g];
#pragma unroll
            for (int u = 0; u < 8; u++) a = fmaf(wh[g * 8 + u], h[u], a);
            gh[g] = a;
        }
#pragma unroll
        for (int u = 0; u < 8; u++) {
            float rg = 1.f / (1.f + expf(-(gi[u] + gh[u])));
            float zg = 1.f / (1.f + expf(-(gi[8 + u] + gh[8 + u])));
            float ng = tanhf(gi[16 + u] + rg * gh[16 + u]);
            h[u] = (1.f - zg) * ng + zg * h[u];
        }
    }
#pragma unroll
    for (int u = 0; u < 8; u++) HS[(size_t)n * 8 + u] = h[u];
}

// ---------------- head ----------------
__global__ void k_final(const float* __restrict__ H1, const float* __restrict__ HS,
                        const float* __restrict__ lin_w, const float* __restrict__ lin_b,
                        const float* __restrict__ hw_w, const float* __restrict__ hw_b,
                        const float* __restrict__ XR, float* __restrict__ out)
{
    int id = blockIdx.x * blockDim.x + threadIdx.x;
    if (id >= 82176) return;
    int b = id / 321, m = id - b * 321;
    const float* wr = lin_w + (size_t)m * 320;
    float acc = lin_b[m];
    const float* h1 = H1 + (size_t)b * 128;
    for (int j = 0; j < 128; j++) acc = fmaf(wr[j], h1[j], acc);
    const float* hsv = HS + (size_t)b * 192;
    for (int q = 0; q < 192; q++) acc = fmaf(wr[128 + q], hsv[q], acc);
    float z = hw_b[0];
    const float* xr = XR + (size_t)id * 192 + 168;
    for (int k = 0; k < 24; k++) z = fmaf(hw_w[k], xr[k], z);
    out[id] = acc + z;
}

// ---------------- host driver ----------------
struct NodeIO { int wi; const float* Z; float* EU; float* OU; };

static void run_nodes(const float* b1, const float* b2, float* pool,
                      const NodeIO* nd, int cnt, int Th)
{
    uint32_t* W1pk = (uint32_t*)(pool + O_W1PK);
    uint32_t* W2pk = (uint32_t*)(pool + O_W2PK);
    auto W1 = [&](int wi, int j){ return W1pk + (size_t)(wi * 4 + j) * 384 * KP1; };
    auto W2 = [&](int wi, int j){ return W2pk + (size_t)(wi * 4 + j) * 384 * KP2; };
    auto B1 = [&](int wi, int j){ return b1 + (size_t)(wi * 4 + j) * 321; };
    auto B2 = [&](int wi, int j){ return b2 + (size_t)(wi * 4 + j) * 321; };

    float* DQ[4]; float* CQ[4]; float* YA[4]; float* YB[4];
    for (int n = 0; n < 4; n++) {
        DQ[n] = pool + O_DQ + (size_t)n * 98 * FU;
        CQ[n] = pool + O_CQ + (size_t)n * 98 * FU;
        YA[n] = pool + O_YA + (size_t)n * 98 * FU;
        YB[n] = pool + O_YB + (size_t)n * 98 * FU;
    }

    dim3 g1((256 * (Th + 2)) / 64, 3, 2 * cnt);
    dim3 g2((256 * Th) / 64, 3, 2 * cnt);

    // conv1 phi/psi: B = strided e/o view of Z (fp32), replication pad 3
    {
        GA a{};
        for (int n = 0; n < cnt; n++) {
            a.z[2*n]   = {W1(nd[n].wi, 0), nd[n].Z, B1(nd[n].wi, 0), nullptr, YA[n], 0, 0, 0};
            a.z[2*n+1] = {W1(nd[n].wi, 1), nd[n].Z, B1(nd[n].wi, 1), nullptr, YB[n], 1, 0, 0};
        }
        a.Mrows = 321; a.Kdim = 1605; a.Kpad = KP1; a.Cin = 321; a.Tout = Th + 2;
        a.LB = 2 * Th; a.sB = 2; a.pad = 3; a.TmaxB = Th - 1;
        a.L1 = 0; a.s1s = 0; a.MoutLd = 321;
        k_mma<5, false><<<g1, 256>>>(a);
    }
    // conv2 phi/psi: mode 1, src1 = o/e strided views of Z
    {
        GA a{};
        for (int n = 0; n < cnt; n++) {
            a.z[2*n]   = {W2(nd[n].wi, 0), YA[n], B2(nd[n].wi, 0), nd[n].Z, DQ[n], 0, 1, 1};
            a.z[2*n+1] = {W2(nd[n].wi, 1), YB[n], B2(nd[n].wi, 1), nd[n].Z, CQ[n], 0, 0, 1};
        }
        a.Mrows = 321; a.Kdim = 963; a.Kpad = KP2; a.Cin = 321; a.Tout = Th;
        a.LB = Th + 2; a.sB = 1; a.pad = 0; a.TmaxB = Th + 1;
        a.L1 = 2 * Th; a.s1s = 2; a.MoutLd = 321;
        k_mma<3, false><<<g2, 256>>>(a);
    }
    // conv1 U/P: B = D/C dense, pad 3
    {
        GA a{};
        for (int n = 0; n < cnt; n++) {
            a.z[2*n]   = {W1(nd[n].wi, 2), DQ[n], B1(nd[n].wi, 2), nullptr, YA[n], 0, 0, 0};
            a.z[2*n+1] = {W1(nd[n].wi, 3), CQ[n], B1(nd[n].wi, 3), nullptr, YB[n], 0, 0, 0};
        }
        a.Mrows = 321; a.Kdim = 1605; a.Kpad = KP1; a.Cin = 321; a.Tout = Th + 2;
        a.LB = Th; a.sB = 1; a.pad = 3; a.TmaxB = Th - 1;
        a.L1 = 0; a.s1s = 0; a.MoutLd = 321;
        k_mma<5, false><<<g1, 256>>>(a);
    }
    // conv2 U/P: EU = C + tanh (mode 2), OU = D - tanh (mode 3)
    {
        GA a{};
        for (int n = 0; n < cnt; n++) {
            a.z[2*n]   = {W2(nd[n].wi, 2), YA[n], B2(nd[n].wi, 2), CQ[n], nd[n].EU, 0, 0, 2};
            a.z[2*n+1] = {W2(nd[n].wi, 3), YB[n], B2(nd[n].wi, 3), DQ[n], nd[n].OU, 0, 0, 3};
        }
        a.Mrows = 321; a.Kdim = 963; a.Kpad = KP2; a.Cin = 321; a.Tout = Th;
        a.LB = Th + 2; a.sB = 1; a.pad = 0; a.TmaxB = Th + 1;
        a.L1 = Th; a.s1s = 1; a.MoutLd = 321;
        k_mma<3, false><<<g2, 256>>>(a);
    }
}

extern "C" void kernel_launch(void* const* d_in, const int* in_sizes, int n_in,
                              void* d_out, int out_size)
{
    float* pool = nullptr;
    cudaGetSymbolAddress((void**)&pool, g_pool);

    const float* x     = (const float*)d_in[0];
    const float* tw1   = (const float*)d_in[1];
    const float* tb1   = (const float*)d_in[2];
    const float* tw2   = (const float*)d_in[3];
    const float* tb2   = (const float*)d_in[4];
    const float* c1w   = (const float*)d_in[5];
    const float* c1b   = (const float*)d_in[6];
    const float* g1wih = (const float*)d_in[7];
    const float* g1whh = (const float*)d_in[8];
    const float* g1bih = (const float*)d_in[9];
    const float* g1bhh = (const float*)d_in[10];
    const float* gswih = (const float*)d_in[11];
    const float* gswhh = (const float*)d_in[12];
    const float* gsbih = (const float*)d_in[13];
    const float* gsbhh = (const float*)d_in[14];
    const float* linw  = (const float*)d_in[15];
    const float* linb  = (const float*)d_in[16];
    const float* hww   = (const float*)d_in[17];
    const float* hwb   = (const float*)d_in[18];

    float* Z0   = pool + O_Z0;
    float* XR   = pool + O_XR;
    float* EU0  = pool + O_EU0;  float* OU0  = pool + O_OU0;
    float* EU1A = pool + O_EU1A; float* OU1A = pool + O_OU1A;
    float* EU1B = pool + O_EU1B; float* OU1B = pool + O_OU1B;
    float* EU2[4]; float* OU2[4];
    for (int n = 0; n < 4; n++) {
        EU2[n] = pool + O_EU2 + (size_t)n * 24 * FU;
        OU2[n] = pool + O_OU2 + (size_t)n * 24 * FU;
    }
    float* R1 = pool + O_R1; float* R4 = pool + O_R4;
    float* R2 = pool + O_R2; float* R3 = pool + O_R3;
    float* CC  = pool + O_CC;
    float* GIb = pool + O_GI;
    float* H1  = pool + O_H1;
    float* HS  = pool + O_HS;
    uint32_t* WSpk = (uint32_t*)(pool + O_WSPK);
    uint32_t* WGpk = (uint32_t*)(pool + O_WGPK);

    // 0) weight conversion (split-bf16, padded)
    k_cvt_w<<<8192, 256>>>(tw1, (uint32_t*)(pool + O_W1PK), 28, 321, 384, 1605, KP1);
    k_cvt_w<<<8192, 256>>>(tw2, (uint32_t*)(pool + O_W2PK), 28, 321, 384, 963, KP2);
    k_cvt_w<<<1024, 256>>>(c1w, WSpk, 1, 128, 128, 1926, KPS);
    k_cvt_w<<<192, 256>>>(g1wih, WGpk, 1, 384, 384, 128, KPG);

    // 1) x -> BMT layout
    k_transpose_x<<<1024, 256>>>(x, Z0);

    // 2) SCINet tree, level-batched
    NodeIO n0[1] = {{0, Z0, EU0, OU0}};
    run_nodes(tb1, tb2, pool, n0, 1, 96);
    NodeIO n1[2] = {{1, EU0, EU1A, OU1A}, {4, OU0, EU1B, OU1B}};
    run_nodes(tb1, tb2, pool, n1, 2, 48);
    NodeIO n2[4] = {{2, EU1A, EU2[0], OU2[0]}, {3, OU1A, EU2[1], OU2[1]},
                    {5, EU1B, EU2[2], OU2[2]}, {6, OU1B, EU2[3], OU2[3]}};
    run_nodes(tb1, tb2, pool, n2, 4, 24);

    // zip-up-the-pants
    k_zip<<<512, 256>>>(EU2[0], OU2[0], R2, 24);
    k_zip<<<512, 256>>>(EU2[1], OU2[1], R3, 24);
    k_zip<<<1024, 256>>>(R2, R3, R1, 48);
    k_zip<<<512, 256>>>(EU2[2], OU2[2], R2, 24);
    k_zip<<<512, 256>>>(EU2[3], OU2[3], R3, 24);
    k_zip<<<1024, 256>>>(R2, R3, R4, 48);
    k_zip<<<1024, 256>>>(R1, R4, Z0, 96);     // res1 -> Z0

    // 3) xr = x + res1
    k_xr<<<1024, 256>>>(x, Z0, XR);

    // 4) conv stage (full-width Conv2d + relu): r = k*321 + m
    {
        GA a{};
        a.z[0] = {WSpk, XR, c1b, nullptr, CC, 0, 0, 4};
        a.Mrows = 128; a.Kdim = 1926; a.Kpad = KPS; a.Cin = 321; a.Tout = 187;
        a.LB = 192; a.sB = 1; a.pad = 0; a.TmaxB = 191;
        a.L1 = 0; a.s1s = 0; a.MoutLd = 128;
        k_mma<321, true><<<dim3(748, 1, 1), 256>>>(a);
    }

    // 5) GRU1 input projection (transposed store)
    {
        GA a{};
        a.z[0] = {WGpk, CC, g1bih, nullptr, GIb, 0, 0, 5};
        a.Mrows = 384; a.Kdim = 128; a.Kpad = KPG; a.Cin = 128; a.Tout = 187;
        a.LB = 187; a.sB = 1; a.pad = 0; a.TmaxB = 186;
        a.L1 = 0; a.s1s = 0; a.MoutLd = 384;
        k_mma<1, false><<<dim3(748, 3, 1), 256>>>(a);
    }

    // 6) GRU1 recurrence
    k_gru1<<<128, 384>>>(GIb, g1whh, g1bhh, H1);

    // 7) skip GRU
    k_skipgru<<<48, 128>>>(CC, gswih, gswhh, gsbih, gsbhh, HS);

    // 8) head
    k_final<<<(82176 + 255) / 256, 256>>>(H1, HS, linw, linb, hww, hwb, XR,
                                          (float*)d_out);
}

// round 15
// speedup vs baseline: 1.0574x; 1.0386x over previous
#include <cuda_runtime.h>
#include <cuda_bf16.h>
#include <math.h>
#include <stdint.h>

// ---------------- dims ----------------
static constexpr int B_ = 256, M_ = 321, P_ = 192;
static constexpr size_t FU = (size_t)B_ * M_; // 82176

// padded K dims (multiples of 16)
static constexpr int KP1 = 1616;   // 1605
static constexpr int KP2 = 976;    // 963
static constexpr int KPS = 1936;   // 1926
static constexpr int KPG = 128;    // 128

// ---------------- scratch pool offsets (in 4-byte elems) ----------------
static constexpr size_t O_Z0   = 0;                        // 192*FU
static constexpr size_t O_XR   = O_Z0   + 192*FU;          // 192*FU
static constexpr size_t O_EU0  = O_XR   + 192*FU;          // 96*FU
static constexpr size_t O_OU0  = O_EU0  +  96*FU;
static constexpr size_t O_EU1A = O_OU0  +  96*FU;          // 48*FU
static constexpr size_t O_OU1A = O_EU1A +  48*FU;
static constexpr size_t O_EU1B = O_OU1A +  48*FU;
static constexpr size_t O_OU1B = O_EU1B +  48*FU;
static constexpr size_t O_EU2  = O_OU1B +  48*FU;          // 4 x 24*FU
static constexpr size_t O_OU2  = O_EU2  + (size_t)4*24*FU; // 4 x 24*FU
static constexpr size_t O_R1   = O_OU2  + (size_t)4*24*FU; // 96*FU
static constexpr size_t O_R4   = O_R1   +  96*FU;
static constexpr size_t O_R2   = O_R4   +  96*FU;          // 48*FU
static constexpr size_t O_R3   = O_R2   +  48*FU;
static constexpr size_t O_DQ   = O_R3   +  48*FU;          // 4 x 98*FU
static constexpr size_t O_CQ   = O_DQ   + (size_t)4*98*FU;
static constexpr size_t O_YA   = O_CQ   + (size_t)4*98*FU;
static constexpr size_t O_YB   = O_YA   + (size_t)4*98*FU;
static constexpr size_t O_CC   = O_YB   + (size_t)4*98*FU; // 256*128*187
static constexpr size_t O_GI   = O_CC   + (size_t)B_*128*187;
static constexpr size_t O_H1   = O_GI   + (size_t)47872*384;
static constexpr size_t O_HS   = O_H1   + (size_t)B_*128;
static constexpr size_t O_W1PK = O_HS   + (size_t)6144*8;      // 28*384*KP1
static constexpr size_t O_W2PK = O_W1PK + (size_t)28*384*KP1;  // 28*384*KP2
static constexpr size_t O_WSPK = O_W2PK + (size_t)28*384*KP2;  // 128*KPS
static constexpr size_t O_WGPK = O_WSPK + (size_t)128*KPS;     // 384*KPG
static constexpr size_t POOLN  = O_WGPK + (size_t)384*KPG + 64;

__device__ __align__(16) float g_pool[POOLN];

// ---------------- fast transcendentals ----------------
__device__ __forceinline__ float ftanh_(float x) {
    float e = __expf(2.f * x);
    return 1.f - __fdividef(2.f, e + 1.f);
}
__device__ __forceinline__ float fsig_(float x) {
    return __fdividef(1.f, 1.f + __expf(-x));
}

// ---------------- split-bf16 packing: u32 = hi | lo<<16 ----------------
__device__ __forceinline__ uint32_t pack2(float v) {
    __nv_bfloat16 h = __float2bfloat16(v);
    float hf = __bfloat162float(h);
    __nv_bfloat16 l = __float2bfloat16(v - hf);
    return (uint32_t)__bfloat16_as_ushort(h) |
           ((uint32_t)__bfloat16_as_ushort(l) << 16);
}

// mma.sync m16n8k16 bf16, fp32 accumulate
__device__ __forceinline__ void mma16816(float* c, const uint32_t* a, const uint32_t* b) {
    asm volatile(
        "mma.sync.aligned.m16n8k16.row.col.f32.bf16.bf16.f32 "
        "{%0,%1,%2,%3}, {%4,%5,%6,%7}, {%8,%9}, {%0,%1,%2,%3};"
        : "+f"(c[0]), "+f"(c[1]), "+f"(c[2]), "+f"(c[3])
        : "r"(a[0]), "r"(a[1]), "r"(a[2]), "r"(a[3]), "r"(b[0]), "r"(b[1]));
}

__device__ __forceinline__ void ldsm_x4(uint32_t* r, uint32_t saddr) {
    asm volatile("ldmatrix.sync.aligned.m8n8.x4.shared.b16 {%0,%1,%2,%3}, [%4];"
        : "=r"(r[0]), "=r"(r[1]), "=r"(r[2]), "=r"(r[3]) : "r"(saddr));
}
__device__ __forceinline__ void ldsm_x2t(uint32_t* r, uint32_t saddr) {
    asm volatile("ldmatrix.sync.aligned.m8n8.x2.trans.shared.b16 {%0,%1}, [%2];"
        : "=r"(r[0]), "=r"(r[1]) : "r"(saddr));
}

// ---------------- elementwise kernels ----------------
__global__ void k_transpose_x(const float* __restrict__ x, float* __restrict__ z)
{
    size_t n = FU * 192;
    for (size_t i = (size_t)blockIdx.x * blockDim.x + threadIdx.x; i < n;
         i += (size_t)gridDim.x * blockDim.x) {
        int t = (int)(i % 192);
        size_t u = i / 192;
        int m = (int)(u % 321);
        int b = (int)(u / 321);
        z[i] = x[((size_t)b * 192 + t) * 321 + m];
    }
}

__global__ void k_xr(const float* __restrict__ x, const float* __restrict__ r,
                     float* __restrict__ xr)
{
    size_t n = FU * 192;
    for (size_t i = (size_t)blockIdx.x * blockDim.x + threadIdx.x; i < n;
         i += (size_t)gridDim.x * blockDim.x) {
        int t = (int)(i % 192);
        size_t u = i / 192;
        int m = (int)(u % 321);
        int b = (int)(u / 321);
        xr[i] = x[((size_t)b * 192 + t) * 321 + m] + r[i];
    }
}

__global__ void k_zip(const float* __restrict__ a, const float* __restrict__ b,
                      float* __restrict__ o, int Th)
{
    size_t n = FU * (size_t)Th;
    for (size_t i = (size_t)blockIdx.x * blockDim.x + threadIdx.x; i < n;
         i += (size_t)gridDim.x * blockDim.x) {
        int t = (int)(i % Th);
        size_t u = i / Th;
        float* orow = o + u * (size_t)(2 * Th);
        orow[2 * t]     = a[i];
        orow[2 * t + 1] = b[i];
    }
}

// weights -> packed split-bf16, zero-padded to (rowsPad, Kpad)
__global__ void k_cvt_w(const float* __restrict__ w, uint32_t* __restrict__ o,
                        int nconv, int rows, int rowsPad, int Kdim, int Kpad)
{
    size_t n = (size_t)nconv * rowsPad * Kpad;
    for (size_t i = (size_t)blockIdx.x * blockDim.x + threadIdx.x; i < n;
         i += (size_t)gridDim.x * blockDim.x) {
        size_t per = (size_t)rowsPad * Kpad;
        int c = (int)(i / per);
        size_t rem = i - (size_t)c * per;
        int row = (int)(rem / Kpad);
        int r = (int)(rem - (size_t)row * Kpad);
        float v = (row < rows && r < Kdim)
                ? w[((size_t)c * rows + row) * Kdim + r] : 0.f;
        o[i] = pack2(v);
    }
}

// ================= HMMA split-bf16 implicit-GEMM conv =================
struct ZP {
    const uint32_t* A; const float* B; const float* bias; const float* s1;
    float* out; int qB; int qS; int mode;
};
struct GA {
    ZP z[8];
    int Mrows, Kdim, Kpad, Cin, Tout;
    int LB, sB, pad, TmaxB;
    int L1, s1s;
    int MoutLd;
};

static constexpr int ASTR = 20;   // A row stride u32 (8 hi + 8 lo + 4 pad)
static constexpr int BSTR = 68;   // B row stride u32 (64 data + 4 pad)
static constexpr int ASTAGE = 128 * ASTR;   // u32
static constexpr int BARR = 16 * BSTR;      // u32 per array

template<int D, bool SWAP>
__global__ __launch_bounds__(256, 2) void k_mma(GA ga)
{
    __shared__ uint32_t smA[2][ASTAGE];        // [stage][row*ASTR + part*8 + kpair]
    __shared__ uint32_t smB[2][2][BARR];       // [stage][hi/lo][k*BSTR + colpair]

    const ZP zp = ga.z[blockIdx.z];
    const int tid = threadIdx.x;
    const int lane = tid & 31;
    const int wid = tid >> 5;
    const int wm = wid & 1;          // 0..1  (M warps)
    const int wn = wid >> 1;         // 0..3  (N warps)
    const int g = lane >> 2;         // 0..7
    const int t4 = lane & 3;         // 0..3
    const int colBase = blockIdx.x * 128;
    const int rowBase = blockIdx.y * 128;
    const int Mrows = ga.Mrows;

    const int Kpad = ga.Kpad, Kd = ga.Kdim;
    const int LB = ga.LB, sB = ga.sB, Tmax = ga.TmaxB;

    // ---- A fill addressing ----
    const int frow = tid >> 2;                // 0..63
    const int fk0 = (tid & 3) * 4;            // k offset 0,4,8,12
    const uint32_t* Arow0 = zp.A + (size_t)(rowBase + frow) * Kpad + fk0;
    const uint32_t* Arow1 = Arow0 + (size_t)64 * Kpad;

    // ---- B fill addressing: thread = (kg, cp); cols 2cp, 2cp+1 ----
    const int kg = tid >> 6;                  // 0..3 -> k rows 4kg..4kg+3
    const int cp = tid & 63;                  // col pair
    const float* Bb[2];
    int tb[2];
#pragma unroll
    for (int c = 0; c < 2; c++) {
        int col = colBase + 2 * cp + c;
        int bb = col / ga.Tout;
        int t  = col - bb * ga.Tout;
        Bb[c] = zp.B + (size_t)bb * ga.Cin * LB + zp.qB;
        tb[c] = t - ga.pad;
    }

    float acc[4][4][4];
#pragma unroll
    for (int i = 0; i < 4; i++)
#pragma unroll
        for (int j = 0; j < 4; j++)
#pragma unroll
            for (int q = 0; q < 4; q++) acc[i][j][q] = 0.f;

    uint4 av[2];
    float bv[2][4];

    auto fetch = [&](int kt) {
        const int kg16 = kt << 4;
        av[0] = *(const uint4*)(Arow0 + kg16);
        av[1] = *(const uint4*)(Arow1 + kg16);
#pragma unroll
        for (int c = 0; c < 2; c++) {
#pragma unroll
            for (int kk = 0; kk < 4; kk++) {
                int r = kg16 + kg * 4 + kk;
                float v = 0.f;
                if (r < Kd) {
                    int cin, off;
                    if (SWAP) { cin = r % D; off = r / D; }
                    else      { cin = r / D; off = r % D; }
                    int tc = tb[c] + off;
                    tc = tc < 0 ? 0 : (tc > Tmax ? Tmax : tc);
                    v = Bb[c][(size_t)cin * LB + sB * tc];
                }
                bv[c][kk] = v;
            }
        }
    };
    auto store = [&](int s) {
        const int kq = fk0 >> 1;
        // A: rows frow, frow+64
#pragma unroll
        for (int p = 0; p < 2; p++) {
            uint4 v = (p == 0) ? av[0] : av[1];
            int base = (frow + 64 * p) * ASTR + kq;
            *(uint2*)&smA[s][base] =
                make_uint2(__byte_perm(v.x, v.y, 0x5410), __byte_perm(v.z, v.w, 0x5410));
            *(uint2*)&smA[s][base + 8] =
                make_uint2(__byte_perm(v.x, v.y, 0x7632), __byte_perm(v.z, v.w, 0x7632));
        }
        // B: k rows 4kg..4kg+3, col pair cp
#pragma unroll
        for (int kk = 0; kk < 4; kk++) {
            uint32_t p0 = pack2(bv[0][kk]);
            uint32_t p1 = pack2(bv[1][kk]);
            int idx = (4 * kg + kk) * BSTR + cp;
            smB[s][0][idx] = __byte_perm(p0, p1, 0x5410);
            smB[s][1][idx] = __byte_perm(p0, p1, 0x7632);
        }
    };

    // ---- ldmatrix per-thread addresses ----
    uint32_t aBase = (uint32_t)__cvta_generic_to_shared(&smA[0][0]);
    uint32_t bBase = (uint32_t)__cvta_generic_to_shared(&smB[0][0][0]);
    const int r16 = lane & 15;
    const uint32_t aRowOff = (uint32_t)(r16 * ASTR * 4) + ((lane >> 4) << 4);
    const uint32_t bRowOff = (uint32_t)(r16 * BSTR * 4) + (uint32_t)((32 * wn) * 2);

    const int nCh = Kpad >> 4;

    fetch(0);
    store(0);
    __syncthreads();
    for (int kt = 0; kt < nCh; kt++) {
        if (kt + 1 < nCh) fetch(kt + 1);

        const int s = kt & 1;
        const uint32_t aS = aBase + (uint32_t)(s * ASTAGE * 4) + aRowOff;
        const uint32_t bHiS = bBase + (uint32_t)((s * 2) * BARR * 4) + bRowOff;
        const uint32_t bLoS = bHiS + (uint32_t)(BARR * 4);

        uint32_t bh[4][2], bl[4][2];
#pragma unroll
        for (int j = 0; j < 4; j++) {
            ldsm_x2t(bh[j], bHiS + j * 16);
            ldsm_x2t(bl[j], bLoS + j * 16);
        }
#pragma unroll
        for (int i = 0; i < 4; i++) {
            uint32_t ah[4], al[4];
            uint32_t ai = aS + (uint32_t)((64 * wm + 16 * i) * ASTR * 4);
            ldsm_x4(ah, ai);
            ldsm_x4(al, ai + 32);
#pragma unroll
            for (int j = 0; j < 4; j++) {
                mma16816(acc[i][j], ah, bh[j]);
                mma16816(acc[i][j], ah, bl[j]);
                mma16816(acc[i][j], al, bh[j]);
            }
        }
        if (kt + 1 < nCh) store((kt + 1) & 1);
        __syncthreads();
    }

    // ---- epilogue (fast transcendentals) ----
    const int mode = zp.mode;
#pragma unroll
    for (int i = 0; i < 4; i++) {
        int row0 = rowBase + 64 * wm + 16 * i + g;
#pragma unroll
        for (int rr = 0; rr < 2; rr++) {
            int row = row0 + 8 * rr;
            if (row >= Mrows) continue;
            float bvs = zp.bias[row];
#pragma unroll
            for (int j = 0; j < 4; j++) {
#pragma unroll
                for (int cc = 0; cc < 2; cc++) {
                    int col = colBase + 32 * wn + 8 * j + 2 * t4 + cc;
                    float v = acc[i][j][rr * 2 + cc] + bvs;
                    if (mode == 5) {
                        zp.out[(size_t)col * ga.MoutLd + row] = v;
                        continue;
                    }
                    int bb = col / ga.Tout;
                    int t  = col - bb * ga.Tout;
                    size_t oi = ((size_t)bb * ga.MoutLd + row) * ga.Tout + t;
                    if (mode == 0)      v = v > 0.f ? v : 0.01f * v;
                    else if (mode == 4) v = fmaxf(v, 0.f);
                    else {
                        float s1v = zp.s1[((size_t)bb * 321 + row) * ga.L1
                                          + ga.s1s * t + zp.qS];
                        if (mode == 1)      v = s1v * __expf(ftanh_(v));
                        else if (mode == 2) v = s1v + ftanh_(v);
                        else                v = s1v - ftanh_(v);
                    }
                    zp.out[oi] = v;
                }
            }
        }
    }
}

// ---------------- GRU1: persistent recurrence ----------------
__global__ __launch_bounds__(384, 1) void k_gru1(
    const float* __restrict__ GI, const float* __restrict__ whh,
    const float* __restrict__ bhh, float* __restrict__ H1)
{
    __shared__ __align__(16) float hs[2][128];
    __shared__ float gs[2][384];
    const int tid = threadIdx.x;
    const int b0 = blockIdx.x * 2;

    float w[128];
#pragma unroll
    for (int k = 0; k < 128; k++) w[k] = whh[(size_t)tid * 128 + k];
    const float bh = bhh[tid];

    if (tid < 128) { hs[0][tid] = 0.f; hs[1][tid] = 0.f; }
    __syncthreads();

    for (int t = 0; t < 187; t++) {
        float g0 = bh, g1 = bh;
#pragma unroll
        for (int k4 = 0; k4 < 32; k4++) {
            float4 h0 = *(const float4*)&hs[0][k4 * 4];
            float4 h1 = *(const float4*)&hs[1][k4 * 4];
            g0 = fmaf(w[k4*4+0], h0.x, g0); g1 = fmaf(w[k4*4+0], h1.x, g1);
            g0 = fmaf(w[k4*4+1], h0.y, g0); g1 = fmaf(w[k4*4+1], h1.y, g1);
            g0 = fmaf(w[k4*4+2], h0.z, g0); g1 = fmaf(w[k4*4+2], h1.z, g1);
            g0 = fmaf(w[k4*4+3], h0.w, g0); g1 = fmaf(w[k4*4+3], h1.w, g1);
        }
        gs[0][tid] = g0;
        gs[1][tid] = g1;
        __syncthreads();

        float hnew = 0.f;
        int bb = 0, j = 0;
        if (tid < 256) {
            bb = tid >> 7; j = tid & 127;
            size_t base = ((size_t)(b0 + bb) * 187 + t) * 384;
            float ir = GI[base + j], iz = GI[base + 128 + j], inn = GI[base + 256 + j];
            float hr = gs[bb][j], hz = gs[bb][128 + j], hn = gs[bb][256 + j];
            float rg = fsig_(ir + hr);
            float zg = fsig_(iz + hz);
            float ng = ftanh_(inn + rg * hn);
            hnew = (1.f - zg) * ng + zg * hs[bb][j];
        }
        __syncthreads();
        if (tid < 256) hs[bb][j] = hnew;
        __syncthreads();
    }
    if (tid < 256) H1[(size_t)(b0 + (tid >> 7)) * 128 + (tid & 127)] = hs[tid >> 7][tid & 127];
}

// ---------------- skip GRU ----------------
__global__ __launch_bounds__(128) void k_skipgru(
    const float* __restrict__ C, const float* __restrict__ wih,
    const float* __restrict__ whh, const float* __restrict__ bih,
    const float* __restrict__ bhh, float* __restrict__ HS)
{
    __shared__ float wi[24 * 128];
    __shared__ float wh[24 * 8];
    __shared__ float bi[24], bh[24];
    const int tid = threadIdx.x;
    for (int i = tid; i < 24 * 128; i += 128) wi[i] = wih[i];
    for (int i = tid; i < 24 * 8; i += 128) wh[i] = whh[i];
    if (tid < 24) { bi[tid] = bih[tid]; bh[tid] = bhh[tid]; }
    __syncthreads();

    const int n = blockIdx.x * 128 + tid;
    const int b = n / 24, sk = n - b * 24;
    float h[8];
#pragma unroll
    for (int u = 0; u < 8; u++) h[u] = 0.f;

    for (int pt = 0; pt < 7; pt++) {
        int l = 19 + pt * 24 + sk;
        float gi[24];
#pragma unroll
        for (int g = 0; g < 24; g++) gi[g] = bi[g];
        for (int ch = 0; ch < 128; ch++) {
            float xv = C[((size_t)b * 128 + ch) * 187 + l];
#pragma unroll
            for (int g = 0; g < 24; g++) gi[g] = fmaf(wi[g * 128 + ch], xv, gi[g]);
        }
        float gh[24];
#pragma unroll
        for (int g = 0; g < 24; g++) {
            float a = bh[g];
#pragma unroll
            for (int u = 0; u < 8; u++) a = fmaf(wh[g * 8 + u], h[u], a);
            gh[g] = a;
        }
#pragma unroll
        for (int u = 0; u < 8; u++) {
            float rg = fsig_(gi[u] + gh[u]);
            float zg = fsig_(gi[8 + u] + gh[8 + u]);
            float ng = ftanh_(gi[16 + u] + rg * gh[16 + u]);
            h[u] = (1.f - zg) * ng + zg * h[u];
        }
    }
#pragma unroll
    for (int u = 0; u < 8; u++) HS[(size_t)n * 8 + u] = h[u];
}

// ---------------- head ----------------
__global__ void k_final(const float* __restrict__ H1, const float* __restrict__ HS,
                        const float* __restrict__ lin_w, const float* __restrict__ lin_b,
                        const float* __restrict__ hw_w, const float* __restrict__ hw_b,
                        const float* __restrict__ XR, float* __restrict__ out)
{
    int id = blockIdx.x * blockDim.x + threadIdx.x;
    if (id >= 82176) return;
    int b = id / 321, m = id - b * 321;
    const float* wr = lin_w + (size_t)m * 320;
    float acc = lin_b[m];
    const float* h1 = H1 + (size_t)b * 128;
    for (int j = 0; j < 128; j++) acc = fmaf(wr[j], h1[j], acc);
    const float* hsv = HS + (size_t)b * 192;
    for (int q = 0; q < 192; q++) acc = fmaf(wr[128 + q], hsv[q], acc);
    float z = hw_b[0];
    const float* xr = XR + (size_t)id * 192 + 168;
    for (int k = 0; k < 24; k++) z = fmaf(hw_w[k], xr[k], z);
    out[id] = acc + z;
}

// ---------------- host driver ----------------
struct NodeIO { int wi; const float* Z; float* EU; float* OU; };

static void run_nodes(const float* b1, const float* b2, float* pool,
                      const NodeIO* nd, int cnt, int Th)
{
    uint32_t* W1pk = (uint32_t*)(pool + O_W1PK);
    uint32_t* W2pk = (uint32_t*)(pool + O_W2PK);
    auto W1 = [&](int wi, int j){ return W1pk + (size_t)(wi * 4 + j) * 384 * KP1; };
    auto W2 = [&](int wi, int j){ return W2pk + (size_t)(wi * 4 + j) * 384 * KP2; };
    auto B1 = [&](int wi, int j){ return b1 + (size_t)(wi * 4 + j) * 321; };
    auto B2 = [&](int wi, int j){ return b2 + (size_t)(wi * 4 + j) * 321; };

    float* DQ[4]; float* CQ[4]; float* YA[4]; float* YB[4];
    for (int n = 0; n < 4; n++) {
        DQ[n] = pool + O_DQ + (size_t)n * 98 * FU;
        CQ[n] = pool + O_CQ + (size_t)n * 98 * FU;
        YA[n] = pool + O_YA + (size_t)n * 98 * FU;
        YB[n] = pool + O_YB + (size_t)n * 98 * FU;
    }

    dim3 g1((256 * (Th + 2)) / 128, 3, 2 * cnt);
    dim3 g2((256 * Th) / 128, 3, 2 * cnt);

    // conv1 phi/psi: B = strided e/o view of Z (fp32), replication pad 3
    {
        GA a{};
        for (int n = 0; n < cnt; n++) {
            a.z[2*n]   = {W1(nd[n].wi, 0), nd[n].Z, B1(nd[n].wi, 0), nullptr, YA[n], 0, 0, 0};
            a.z[2*n+1] = {W1(nd[n].wi, 1), nd[n].Z, B1(nd[n].wi, 1), nullptr, YB[n], 1, 0, 0};
        }
        a.Mrows = 321; a.Kdim = 1605; a.Kpad = KP1; a.Cin = 321; a.Tout = Th + 2;
        a.LB = 2 * Th; a.sB = 2; a.pad = 3; a.TmaxB = Th - 1;
        a.L1 = 0; a.s1s = 0; a.MoutLd = 321;
        k_mma<5, false><<<g1, 256>>>(a);
    }
    // conv2 phi/psi: mode 1, src1 = o/e strided views of Z
    {
        GA a{};
        for (int n = 0; n < cnt; n++) {
            a.z[2*n]   = {W2(nd[n].wi, 0), YA[n], B2(nd[n].wi, 0), nd[n].Z, DQ[n], 0, 1, 1};
            a.z[2*n+1] = {W2(nd[n].wi, 1), YB[n], B2(nd[n].wi, 1), nd[n].Z, CQ[n], 0, 0, 1};
        }
        a.Mrows = 321; a.Kdim = 963; a.Kpad = KP2; a.Cin = 321; a.Tout = Th;
        a.LB = Th + 2; a.sB = 1; a.pad = 0; a.TmaxB = Th + 1;
        a.L1 = 2 * Th; a.s1s = 2; a.MoutLd = 321;
        k_mma<3, false><<<g2, 256>>>(a);
    }
    // conv1 U/P: B = D/C dense, pad 3
    {
        GA a{};
        for (int n = 0; n < cnt; n++) {
            a.z[2*n]   = {W1(nd[n].wi, 2), DQ[n], B1(nd[n].wi, 2), nullptr, YA[n], 0, 0, 0};
            a.z[2*n+1] = {W1(nd[n].wi, 3), CQ[n], B1(nd[n].wi, 3), nullptr, YB[n], 0, 0, 0};
        }
        a.Mrows = 321; a.Kdim = 1605; a.Kpad = KP1; a.Cin = 321; a.Tout = Th + 2;
        a.LB = Th; a.sB = 1; a.pad = 3; a.TmaxB = Th - 1;
        a.L1 = 0; a.s1s = 0; a.MoutLd = 321;
        k_mma<5, false><<<g1, 256>>>(a);
    }
    // conv2 U/P: EU = C + tanh (mode 2), OU = D - tanh (mode 3)
    {
        GA a{};
        for (int n = 0; n < cnt; n++) {
            a.z[2*n]   = {W2(nd[n].wi, 2), YA[n], B2(nd[n].wi, 2), CQ[n], nd[n].EU, 0, 0, 2};
            a.z[2*n+1] = {W2(nd[n].wi, 3), YB[n], B2(nd[n].wi, 3), DQ[n], nd[n].OU, 0, 0, 3};
        }
        a.Mrows = 321; a.Kdim = 963; a.Kpad = KP2; a.Cin = 321; a.Tout = Th;
        a.LB = Th + 2; a.sB = 1; a.pad = 0; a.TmaxB = Th + 1;
        a.L1 = Th; a.s1s = 1; a.MoutLd = 321;
        k_mma<3, false><<<g2, 256>>>(a);
    }
}

extern "C" void kernel_launch(void* const* d_in, const int* in_sizes, int n_in,
                              void* d_out, int out_size)
{
    float* pool = nullptr;
    cudaGetSymbolAddress((void**)&pool, g_pool);

    const float* x     = (const float*)d_in[0];
    const float* tw1   = (const float*)d_in[1];
    const float* tb1   = (const float*)d_in[2];
    const float* tw2   = (const float*)d_in[3];
    const float* tb2   = (const float*)d_in[4];
    const float* c1w   = (const float*)d_in[5];
    const float* c1b   = (const float*)d_in[6];
    const float* g1wih = (const float*)d_in[7];
    const float* g1whh = (const float*)d_in[8];
    const float* g1bih = (const float*)d_in[9];
    const float* g1bhh = (const float*)d_in[10];
    const float* gswih = (const float*)d_in[11];
    const float* gswhh = (const float*)d_in[12];
    const float* gsbih = (const float*)d_in[13];
    const float* gsbhh = (const float*)d_in[14];
    const float* linw  = (const float*)d_in[15];
    const float* linb  = (const float*)d_in[16];
    const float* hww   = (const float*)d_in[17];
    const float* hwb   = (const float*)d_in[18];

    float* Z0   = pool + O_Z0;
    float* XR   = pool + O_XR;
    float* EU0  = pool + O_EU0;  float* OU0  = pool + O_OU0;
    float* EU1A = pool + O_EU1A; float* OU1A = pool + O_OU1A;
    float* EU1B = pool + O_EU1B; float* OU1B = pool + O_OU1B;
    float* EU2[4]; float* OU2[4];
    for (int n = 0; n < 4; n++) {
        EU2[n] = pool + O_EU2 + (size_t)n * 24 * FU;
        OU2[n] = pool + O_OU2 + (size_t)n * 24 * FU;
    }
    float* R1 = pool + O_R1; float* R4 = pool + O_R4;
    float* R2 = pool + O_R2; float* R3 = pool + O_R3;
    float* CC  = pool + O_CC;
    float* GIb = pool + O_GI;
    float* H1  = pool + O_H1;
    float* HS  = pool + O_HS;
    uint32_t* WSpk = (uint32_t*)(pool + O_WSPK);
    uint32_t* WGpk = (uint32_t*)(pool + O_WGPK);

    // 0) weight conversion (split-bf16, padded)
    k_cvt_w<<<8192, 256>>>(tw1, (uint32_t*)(pool + O_W1PK), 28, 321, 384, 1605, KP1);
    k_cvt_w<<<8192, 256>>>(tw2, (uint32_t*)(pool + O_W2PK), 28, 321, 384, 963, KP2);
    k_cvt_w<<<1024, 256>>>(c1w, WSpk, 1, 128, 128, 1926, KPS);
    k_cvt_w<<<192, 256>>>(g1wih, WGpk, 1, 384, 384, 128, KPG);

    // 1) x -> BMT layout
    k_transpose_x<<<1024, 256>>>(x, Z0);

    // 2) SCINet tree, level-batched
    NodeIO n0[1] = {{0, Z0, EU0, OU0}};
    run_nodes(tb1, tb2, pool, n0, 1, 96);
    NodeIO n1[2] = {{1, EU0, EU1A, OU1A}, {4, OU0, EU1B, OU1B}};
    run_nodes(tb1, tb2, pool, n1, 2, 48);
    NodeIO n2[4] = {{2, EU1A, EU2[0], OU2[0]}, {3, OU1A, EU2[1], OU2[1]},
                    {5, EU1B, EU2[2], OU2[2]}, {6, OU1B, EU2[3], OU2[3]}};
    run_nodes(tb1, tb2, pool, n2, 4, 24);

    // zip-up-the-pants
    k_zip<<<512, 256>>>(EU2[0], OU2[0], R2, 24);
    k_zip<<<512, 256>>>(EU2[1], OU2[1], R3, 24);
    k_zip<<<1024, 256>>>(R2, R3, R1, 48);
    k_zip<<<512, 256>>>(EU2[2], OU2[2], R2, 24);
    k_zip<<<512, 256>>>(EU2[3], OU2[3], R3, 24);
    k_zip<<<1024, 256>>>(R2, R3, R4, 48);
    k_zip<<<1024, 256>>>(R1, R4, Z0, 96);     // res1 -> Z0

    // 3) xr = x + res1
    k_xr<<<1024, 256>>>(x, Z0, XR);

    // 4) conv stage (full-width Conv2d + relu): r = k*321 + m
    {
        GA a{};
        a.z[0] = {WSpk, XR, c1b, nullptr, CC, 0, 0, 4};
        a.Mrows = 128; a.Kdim = 1926; a.Kpad = KPS; a.Cin = 321; a.Tout = 187;
        a.LB = 192; a.sB = 1; a.pad = 0; a.TmaxB = 191;
        a.L1 = 0; a.s1s = 0; a.MoutLd = 128;
        k_mma<321, true><<<dim3(374, 1, 1), 256>>>(a);
    }

    // 5) GRU1 input projection (transposed store)
    {
        GA a{};
        a.z[0] = {WGpk, CC, g1bih, nullptr, GIb, 0, 0, 5};
        a.Mrows = 384; a.Kdim = 128; a.Kpad = KPG; a.Cin = 128; a.Tout = 187;
        a.LB = 187; a.sB = 1; a.pad = 0; a.TmaxB = 186;
        a.L1 = 0; a.s1s = 0; a.MoutLd = 384;
        k_mma<1, false><<<dim3(374, 3, 1), 256>>>(a);
    }

    // 6) GRU1 recurrence
    k_gru1<<<128, 384>>>(GIb, g1whh, g1bhh, H1);

    // 7) skip GRU
    k_skipgru<<<48, 128>>>(CC, gswih, gswhh, gsbih, gsbhh, HS);

    // 8) head
    k_final<<<(82176 + 255) / 256, 256>>>(H1, HS, linw, linb, hww, hwb, XR,
                                          (float*)d_out);
}

// round 16
// speedup vs baseline: 1.0826x; 1.0238x over previous
#include <cuda_runtime.h>
#include <cuda_bf16.h>
#include <math.h>
#include <stdint.h>

// ---------------- dims ----------------
static constexpr int B_ = 256, M_ = 321, P_ = 192;
static constexpr size_t FU = (size_t)B_ * M_; // 82176

// padded K dims (multiples of 16)
static constexpr int KP1 = 1616;   // 1605
static constexpr int KP2 = 976;    // 963
static constexpr int KPS = 1936;   // 1926
static constexpr int KPG = 128;    // 128

// ---------------- scratch pool offsets (in 4-byte elems) ----------------
static constexpr size_t O_Z0   = 0;                        // 192*FU
static constexpr size_t O_XR   = O_Z0   + 192*FU;          // 192*FU
static constexpr size_t O_EU0  = O_XR   + 192*FU;          // 96*FU
static constexpr size_t O_OU0  = O_EU0  +  96*FU;
static constexpr size_t O_EU1A = O_OU0  +  96*FU;          // 48*FU
static constexpr size_t O_OU1A = O_EU1A +  48*FU;
static constexpr size_t O_EU1B = O_OU1A +  48*FU;
static constexpr size_t O_OU1B = O_EU1B +  48*FU;
static constexpr size_t O_EU2  = O_OU1B +  48*FU;          // 4 x 24*FU
static constexpr size_t O_OU2  = O_EU2  + (size_t)4*24*FU; // 4 x 24*FU
static constexpr size_t O_R1   = O_OU2  + (size_t)4*24*FU; // 96*FU
static constexpr size_t O_R4   = O_R1   +  96*FU;
static constexpr size_t O_R2   = O_R4   +  96*FU;          // 48*FU
static constexpr size_t O_R3   = O_R2   +  48*FU;
static constexpr size_t O_DQ   = O_R3   +  48*FU;          // 4 x 98*FU
static constexpr size_t O_CQ   = O_DQ   + (size_t)4*98*FU;
static constexpr size_t O_YA   = O_CQ   + (size_t)4*98*FU;
static constexpr size_t O_YB   = O_YA   + (size_t)4*98*FU;
static constexpr size_t O_CC   = O_YB   + (size_t)4*98*FU; // 256*128*187
static constexpr size_t O_GI   = O_CC   + (size_t)B_*128*187;
static constexpr size_t O_H1   = O_GI   + (size_t)47872*384;
static constexpr size_t O_HS   = O_H1   + (size_t)B_*128;
static constexpr size_t O_W1PK = O_HS   + (size_t)6144*8;      // 28*384*KP1
static constexpr size_t O_W2PK = O_W1PK + (size_t)28*384*KP1;  // 28*384*KP2
static constexpr size_t O_WSPK = O_W2PK + (size_t)28*384*KP2;  // 128*KPS
static constexpr size_t O_WGPK = O_WSPK + (size_t)128*KPS;     // 384*KPG
static constexpr size_t POOLN  = O_WGPK + (size_t)384*KPG + 64;

__device__ __align__(16) float g_pool[POOLN];

// ---------------- fast transcendentals ----------------
__device__ __forceinline__ float ftanh_(float x) {
    float e = __expf(2.f * x);
    return 1.f - __fdividef(2.f, e + 1.f);
}
__device__ __forceinline__ float fsig_(float x) {
    return __fdividef(1.f, 1.f + __expf(-x));
}

// ---------------- split-bf16 packing: u32 = hi | lo<<16 ----------------
__device__ __forceinline__ uint32_t pack2(float v) {
    __nv_bfloat16 h = __float2bfloat16(v);
    float hf = __bfloat162float(h);
    __nv_bfloat16 l = __float2bfloat16(v - hf);
    return (uint32_t)__bfloat16_as_ushort(h) |
           ((uint32_t)__bfloat16_as_ushort(l) << 16);
}

// mma.sync m16n8k16 bf16, fp32 accumulate
__device__ __forceinline__ void mma16816(float* c, const uint32_t* a, const uint32_t* b) {
    asm volatile(
        "mma.sync.aligned.m16n8k16.row.col.f32.bf16.bf16.f32 "
        "{%0,%1,%2,%3}, {%4,%5,%6,%7}, {%8,%9}, {%0,%1,%2,%3};"
        : "+f"(c[0]), "+f"(c[1]), "+f"(c[2]), "+f"(c[3])
        : "r"(a[0]), "r"(a[1]), "r"(a[2]), "r"(a[3]), "r"(b[0]), "r"(b[1]));
}

__device__ __forceinline__ void ldsm_x4(uint32_t* r, uint32_t saddr) {
    asm volatile("ldmatrix.sync.aligned.m8n8.x4.shared.b16 {%0,%1,%2,%3}, [%4];"
        : "=r"(r[0]), "=r"(r[1]), "=r"(r[2]), "=r"(r[3]) : "r"(saddr));
}
__device__ __forceinline__ void ldsm_x4t(uint32_t* r, uint32_t saddr) {
    asm volatile("ldmatrix.sync.aligned.m8n8.x4.trans.shared.b16 {%0,%1,%2,%3}, [%4];"
        : "=r"(r[0]), "=r"(r[1]), "=r"(r[2]), "=r"(r[3]) : "r"(saddr));
}

// ---------------- elementwise kernels ----------------
__global__ void k_transpose_x(const float* __restrict__ x, float* __restrict__ z)
{
    size_t n = FU * 192;
    for (size_t i = (size_t)blockIdx.x * blockDim.x + threadIdx.x; i < n;
         i += (size_t)gridDim.x * blockDim.x) {
        int t = (int)(i % 192);
        size_t u = i / 192;
        int m = (int)(u % 321);
        int b = (int)(u / 321);
        z[i] = x[((size_t)b * 192 + t) * 321 + m];
    }
}

__global__ void k_xr(const float* __restrict__ x, const float* __restrict__ r,
                     float* __restrict__ xr)
{
    size_t n = FU * 192;
    for (size_t i = (size_t)blockIdx.x * blockDim.x + threadIdx.x; i < n;
         i += (size_t)gridDim.x * blockDim.x) {
        int t = (int)(i % 192);
        size_t u = i / 192;
        int m = (int)(u % 321);
        int b = (int)(u / 321);
        xr[i] = x[((size_t)b * 192 + t) * 321 + m] + r[i];
    }
}

__global__ void k_zip(const float* __restrict__ a, const float* __restrict__ b,
                      float* __restrict__ o, int Th)
{
    size_t n = FU * (size_t)Th;
    for (size_t i = (size_t)blockIdx.x * blockDim.x + threadIdx.x; i < n;
         i += (size_t)gridDim.x * blockDim.x) {
        int t = (int)(i % Th);
        size_t u = i / Th;
        float* orow = o + u * (size_t)(2 * Th);
        orow[2 * t]     = a[i];
        orow[2 * t + 1] = b[i];
    }
}

// weights -> packed split-bf16, zero-padded to (rowsPad, Kpad)
__global__ void k_cvt_w(const float* __restrict__ w, uint32_t* __restrict__ o,
                        int nconv, int rows, int rowsPad, int Kdim, int Kpad)
{
    size_t n = (size_t)nconv * rowsPad * Kpad;
    for (size_t i = (size_t)blockIdx.x * blockDim.x + threadIdx.x; i < n;
         i += (size_t)gridDim.x * blockDim.x) {
        size_t per = (size_t)rowsPad * Kpad;
        int c = (int)(i / per);
        size_t rem = i - (size_t)c * per;
        int row = (int)(rem / Kpad);
        int r = (int)(rem - (size_t)row * Kpad);
        float v = (row < rows && r < Kdim)
                ? w[((size_t)c * rows + row) * Kdim + r] : 0.f;
        o[i] = pack2(v);
    }
}

// ================= HMMA split-bf16 implicit-GEMM conv =================
struct ZP {
    const uint32_t* A; const float* B; const float* bias; const float* s1;
    float* out; int qB; int qS; int mode;
};
struct GA {
    ZP z[8];
    int Mrows, Kdim, Kpad, Cin, Tout;
    int LB, sB, pad, TmaxB;
    int L1, s1s;
    int MoutLd;
};

static constexpr int ASTR = 20;   // A row stride u32 (8 hi + 8 lo + 4 pad)
static constexpr int BSTR = 68;   // B row stride u32 (64 data + 4 pad)
static constexpr int ASTAGE = 128 * ASTR;   // u32
static constexpr int BARR = 16 * BSTR;      // u32 per array

template<int D, bool SWAP>
__global__ __launch_bounds__(256, 2) void k_mma(GA ga)
{
    __shared__ uint32_t smA[2][ASTAGE];        // [stage][row*ASTR + part*8 + kpair]
    __shared__ uint32_t smB[2][2][BARR];       // [stage][hi/lo][k*BSTR + colpair]

    const ZP zp = ga.z[blockIdx.z];
    const int tid = threadIdx.x;
    const int lane = tid & 31;
    const int wid = tid >> 5;
    const int wm = wid & 1;          // 0..1  (M warps)
    const int wn = wid >> 1;         // 0..3  (N warps)
    const int g = lane >> 2;         // 0..7
    const int t4 = lane & 3;         // 0..3
    const int colBase = blockIdx.x * 128;
    const int rowBase = blockIdx.y * 128;
    const int Mrows = ga.Mrows;

    const int Kpad = ga.Kpad, Kd = ga.Kdim;
    const int LB = ga.LB, sB = ga.sB, Tmax = ga.TmaxB;

    // ---- A fill addressing ----
    const int frow = tid >> 2;                // 0..63
    const int fk0 = (tid & 3) * 4;            // k offset 0,4,8,12
    const uint32_t* Arow0 = zp.A + (size_t)(rowBase + frow) * Kpad + fk0;
    const uint32_t* Arow1 = Arow0 + (size_t)64 * Kpad;

    // ---- B fill addressing: thread = (kg, cp); cols 2cp, 2cp+1 ----
    const int kg = tid >> 6;                  // 0..3 -> k rows 4kg..4kg+3
    const int cp = tid & 63;                  // col pair
    const float* Bb[2];
    int tb[2];
#pragma unroll
    for (int c = 0; c < 2; c++) {
        int col = colBase + 2 * cp + c;
        int bb = col / ga.Tout;
        int t  = col - bb * ga.Tout;
        Bb[c] = zp.B + (size_t)bb * ga.Cin * LB + zp.qB;
        tb[c] = t - ga.pad;
    }

    float acc[4][4][4];
#pragma unroll
    for (int i = 0; i < 4; i++)
#pragma unroll
        for (int j = 0; j < 4; j++)
#pragma unroll
            for (int q = 0; q < 4; q++) acc[i][j][q] = 0.f;

    uint4 av[2];
    float bv[2][4];

    auto fetch = [&](int kt) {
        const int kg16 = kt << 4;
        av[0] = *(const uint4*)(Arow0 + kg16);
        av[1] = *(const uint4*)(Arow1 + kg16);
#pragma unroll
        for (int c = 0; c < 2; c++) {
#pragma unroll
            for (int kk = 0; kk < 4; kk++) {
                int r = kg16 + kg * 4 + kk;
                float v = 0.f;
                if (r < Kd) {
                    int cin, off;
                    if (SWAP) { cin = r % D; off = r / D; }
                    else      { cin = r / D; off = r % D; }
                    int tc = tb[c] + off;
                    tc = tc < 0 ? 0 : (tc > Tmax ? Tmax : tc);
                    v = Bb[c][(size_t)cin * LB + sB * tc];
                }
                bv[c][kk] = v;
            }
        }
    };
    auto store = [&](int s) {
        const int kq = fk0 >> 1;
        // A: rows frow, frow+64
#pragma unroll
        for (int p = 0; p < 2; p++) {
            uint4 v = (p == 0) ? av[0] : av[1];
            int base = (frow + 64 * p) * ASTR + kq;
            *(uint2*)&smA[s][base] =
                make_uint2(__byte_perm(v.x, v.y, 0x5410), __byte_perm(v.z, v.w, 0x5410));
            *(uint2*)&smA[s][base + 8] =
                make_uint2(__byte_perm(v.x, v.y, 0x7632), __byte_perm(v.z, v.w, 0x7632));
        }
        // B: k rows 4kg..4kg+3, col pair cp
#pragma unroll
        for (int kk = 0; kk < 4; kk++) {
            uint32_t p0 = pack2(bv[0][kk]);
            uint32_t p1 = pack2(bv[1][kk]);
            int idx = (4 * kg + kk) * BSTR + cp;
            smB[s][0][idx] = __byte_perm(p0, p1, 0x5410);
            smB[s][1][idx] = __byte_perm(p0, p1, 0x7632);
        }
    };

    // ---- ldmatrix per-thread addresses ----
    uint32_t aBase = (uint32_t)__cvta_generic_to_shared(&smA[0][0]);
    uint32_t bBase = (uint32_t)__cvta_generic_to_shared(&smB[0][0][0]);
    const int r16 = lane & 15;
    const uint32_t aRowOff = (uint32_t)(r16 * ASTR * 4) + ((lane >> 4) << 4);
    // B x4-trans: lanes 0-15 -> hi array rows, lanes 16-31 -> lo array rows
    const uint32_t bRowOff = (uint32_t)(r16 * BSTR * 4)
                           + (uint32_t)((lane >= 16) ? BARR * 4 : 0)
                           + (uint32_t)((32 * wn) * 2);

    const int nCh = Kpad >> 4;

    fetch(0);
    store(0);
    __syncthreads();
    for (int kt = 0; kt < nCh; kt++) {
        if (kt + 1 < nCh) fetch(kt + 1);

        const int s = kt & 1;
        const uint32_t aS = aBase + (uint32_t)(s * ASTAGE * 4) + aRowOff;
        const uint32_t bS = bBase + (uint32_t)((s * 2) * BARR * 4) + bRowOff;

        uint32_t bf4[4][4];   // per j: {bh0, bh1, bl0, bl1}
#pragma unroll
        for (int j = 0; j < 4; j++)
            ldsm_x4t(bf4[j], bS + j * 16);
#pragma unroll
        for (int i = 0; i < 4; i++) {
            uint32_t ah[4], al[4];
            uint32_t ai = aS + (uint32_t)((64 * wm + 16 * i) * ASTR * 4);
            ldsm_x4(ah, ai);
            ldsm_x4(al, ai + 32);
#pragma unroll
            for (int j = 0; j < 4; j++) {
                mma16816(acc[i][j], ah, &bf4[j][0]);
                mma16816(acc[i][j], ah, &bf4[j][2]);
                mma16816(acc[i][j], al, &bf4[j][0]);
            }
        }
        if (kt + 1 < nCh) store((kt + 1) & 1);
        __syncthreads();
    }

    // ---- epilogue (fast transcendentals) ----
    const int mode = zp.mode;
#pragma unroll
    for (int i = 0; i < 4; i++) {
        int row0 = rowBase + 64 * wm + 16 * i + g;
#pragma unroll
        for (int rr = 0; rr < 2; rr++) {
            int row = row0 + 8 * rr;
            if (row >= Mrows) continue;
            float bvs = zp.bias[row];
#pragma unroll
            for (int j = 0; j < 4; j++) {
#pragma unroll
                for (int cc = 0; cc < 2; cc++) {
                    int col = colBase + 32 * wn + 8 * j + 2 * t4 + cc;
                    float v = acc[i][j][rr * 2 + cc] + bvs;
                    if (mode == 5) {
                        zp.out[(size_t)col * ga.MoutLd + row] = v;
                        continue;
                    }
                    int bb = col / ga.Tout;
                    int t  = col - bb * ga.Tout;
                    size_t oi = ((size_t)bb * ga.MoutLd + row) * ga.Tout + t;
                    if (mode == 0)      v = v > 0.f ? v : 0.01f * v;
                    else if (mode == 4) v = fmaxf(v, 0.f);
                    else {
                        float s1v = zp.s1[((size_t)bb * 321 + row) * ga.L1
                                          + ga.s1s * t + zp.qS];
                        if (mode == 1)      v = s1v * __expf(ftanh_(v));
                        else if (mode == 2) v = s1v + ftanh_(v);
                        else                v = s1v - ftanh_(v);
                    }
                    zp.out[oi] = v;
                }
            }
        }
    }
}

// ---------------- GRU1: persistent recurrence ----------------
__global__ __launch_bounds__(384, 1) void k_gru1(
    const float* __restrict__ GI, const float* __restrict__ whh,
    const float* __restrict__ bhh, float* __restrict__ H1)
{
    __shared__ __align__(16) float hs[2][128];
    __shared__ float gs[2][384];
    const int tid = threadIdx.x;
    const int b0 = blockIdx.x * 2;

    float w[128];
#pragma unroll
    for (int k = 0; k < 128; k++) w[k] = whh[(size_t)tid * 128 + k];
    const float bh = bhh[tid];

    if (tid < 128) { hs[0][tid] = 0.f; hs[1][tid] = 0.f; }
    __syncthreads();

    for (int t = 0; t < 187; t++) {
        float g0 = bh, g1 = bh;
#pragma unroll
        for (int k4 = 0; k4 < 32; k4++) {
            float4 h0 = *(const float4*)&hs[0][k4 * 4];
            float4 h1 = *(const float4*)&hs[1][k4 * 4];
            g0 = fmaf(w[k4*4+0], h0.x, g0); g1 = fmaf(w[k4*4+0], h1.x, g1);
            g0 = fmaf(w[k4*4+1], h0.y, g0); g1 = fmaf(w[k4*4+1], h1.y, g1);
            g0 = fmaf(w[k4*4+2], h0.z, g0); g1 = fmaf(w[k4*4+2], h1.z, g1);
            g0 = fmaf(w[k4*4+3], h0.w, g0); g1 = fmaf(w[k4*4+3], h1.w, g1);
        }
        gs[0][tid] = g0;
        gs[1][tid] = g1;
        __syncthreads();

        float hnew = 0.f;
        int bb = 0, j = 0;
        if (tid < 256) {
            bb = tid >> 7; j = tid & 127;
            size_t base = ((size_t)(b0 + bb) * 187 + t) * 384;
            float ir = GI[base + j], iz = GI[base + 128 + j], inn = GI[base + 256 + j];
            float hr = gs[bb][j], hz = gs[bb][128 + j], hn = gs[bb][256 + j];
            float rg = fsig_(ir + hr);
            float zg = fsig_(iz + hz);
            float ng = ftanh_(inn + rg * hn);
            hnew = (1.f - zg) * ng + zg * hs[bb][j];
        }
        __syncthreads();
        if (tid < 256) hs[bb][j] = hnew;
        __syncthreads();
    }
    if (tid < 256) H1[(size_t)(b0 + (tid >> 7)) * 128 + (tid & 127)] = hs[tid >> 7][tid & 127];
}

// ---------------- skip GRU ----------------
__global__ __launch_bounds__(128) void k_skipgru(
    const float* __restrict__ C, const float* __restrict__ wih,
    const float* __restrict__ whh, const float* __restrict__ bih,
    const float* __restrict__ bhh, float* __restrict__ HS)
{
    __shared__ float wi[24 * 128];
    __shared__ float wh[24 * 8];
    __shared__ float bi[24], bh[24];
    const int tid = threadIdx.x;
    for (int i = tid; i < 24 * 128; i += 128) wi[i] = wih[i];
    for (int i = tid; i < 24 * 8; i += 128) wh[i] = whh[i];
    if (tid < 24) { bi[tid] = bih[tid]; bh[tid] = bhh[tid]; }
    __syncthreads();

    const int n = blockIdx.x * 128 + tid;
    const int b = n / 24, sk = n - b * 24;
    float h[8];
#pragma unroll
    for (int u = 0; u < 8; u++) h[u] = 0.f;

    for (int pt = 0; pt < 7; pt++) {
        int l = 19 + pt * 24 + sk;
        float gi[24];
#pragma unroll
        for (int g = 0; g < 24; g++) gi[g] = bi[g];
        for (int ch = 0; ch < 128; ch++) {
            float xv = C[((size_t)b * 128 + ch) * 187 + l];
#pragma unroll
            for (int g = 0; g < 24; g++) gi[g] = fmaf(wi[g * 128 + ch], xv, gi[g]);
        }
        float gh[24];
#pragma unroll
        for (int g = 0; g < 24; g++) {
            float a = bh[g];
#pragma unroll
            for (int u = 0; u < 8; u++) a = fmaf(wh[g * 8 + u], h[u], a);
            gh[g] = a;
        }
#pragma unroll
        for (int u = 0; u < 8; u++) {
            float rg = fsig_(gi[u] + gh[u]);
            float zg = fsig_(gi[8 + u] + gh[8 + u]);
            float ng = ftanh_(gi[16 + u] + rg * gh[16 + u]);
            h[u] = (1.f - zg) * ng + zg * h[u];
        }
    }
#pragma unroll
    for (int u = 0; u < 8; u++) HS[(size_t)n * 8 + u] = h[u];
}

// ---------------- head ----------------
__global__ void k_final(const float* __restrict__ H1, const float* __restrict__ HS,
                        const float* __restrict__ lin_w, const float* __restrict__ lin_b,
                        const float* __restrict__ hw_w, const float* __restrict__ hw_b,
                        const float* __restrict__ XR, float* __restrict__ out)
{
    int id = blockIdx.x * blockDim.x + threadIdx.x;
    if (id >= 82176) return;
    int b = id / 321, m = id - b * 321;
    const float* wr = lin_w + (size_t)m * 320;
    float acc = lin_b[m];
    const float* h1 = H1 + (size_t)b * 128;
    for (int j = 0; j < 128; j++) acc = fmaf(wr[j], h1[j], acc);
    const float* hsv = HS + (size_t)b * 192;
    for (int q = 0; q < 192; q++) acc = fmaf(wr[128 + q], hsv[q], acc);
    float z = hw_b[0];
    const float* xr = XR + (size_t)id * 192 + 168;
    for (int k = 0; k < 24; k++) z = fmaf(hw_w[k], xr[k], z);
    out[id] = acc + z;
}

// ---------------- host driver ----------------
struct NodeIO { int wi; const float* Z; float* EU; float* OU; };

static void run_nodes(const float* b1, const float* b2, float* pool,
                      const NodeIO* nd, int cnt, int Th)
{
    uint32_t* W1pk = (uint32_t*)(pool + O_W1PK);
    uint32_t* W2pk = (uint32_t*)(pool + O_W2PK);
    auto W1 = [&](int wi, int j){ return W1pk + (size_t)(wi * 4 + j) * 384 * KP1; };
    auto W2 = [&](int wi, int j){ return W2pk + (size_t)(wi * 4 + j) * 384 * KP2; };
    auto B1 = [&](int wi, int j){ return b1 + (size_t)(wi * 4 + j) * 321; };
    auto B2 = [&](int wi, int j){ return b2 + (size_t)(wi * 4 + j) * 321; };

    float* DQ[4]; float* CQ[4]; float* YA[4]; float* YB[4];
    for (int n = 0; n < 4; n++) {
        DQ[n] = pool + O_DQ + (size_t)n * 98 * FU;
        CQ[n] = pool + O_CQ + (size_t)n * 98 * FU;
        YA[n] = pool + O_YA + (size_t)n * 98 * FU;
        YB[n] = pool + O_YB + (size_t)n * 98 * FU;
    }

    dim3 g1((256 * (Th + 2)) / 128, 3, 2 * cnt);
    dim3 g2((256 * Th) / 128, 3, 2 * cnt);

    // conv1 phi/psi: B = strided e/o view of Z (fp32), replication pad 3
    {
        GA a{};
        for (int n = 0; n < cnt; n++) {
            a.z[2*n]   = {W1(nd[n].wi, 0), nd[n].Z, B1(nd[n].wi, 0), nullptr, YA[n], 0, 0, 0};
            a.z[2*n+1] = {W1(nd[n].wi, 1), nd[n].Z, B1(nd[n].wi, 1), nullptr, YB[n], 1, 0, 0};
        }
        a.Mrows = 321; a.Kdim = 1605; a.Kpad = KP1; a.Cin = 321; a.Tout = Th + 2;
        a.LB = 2 * Th; a.sB = 2; a.pad = 3; a.TmaxB = Th - 1;
        a.L1 = 0; a.s1s = 0; a.MoutLd = 321;
        k_mma<5, false><<<g1, 256>>>(a);
    }
    // conv2 phi/psi: mode 1, src1 = o/e strided views of Z
    {
        GA a{};
        for (int n = 0; n < cnt; n++) {
            a.z[2*n]   = {W2(nd[n].wi, 0), YA[n], B2(nd[n].wi, 0), nd[n].Z, DQ[n], 0, 1, 1};
            a.z[2*n+1] = {W2(nd[n].wi, 1), YB[n], B2(nd[n].wi, 1), nd[n].Z, CQ[n], 0, 0, 1};
        }
        a.Mrows = 321; a.Kdim = 963; a.Kpad = KP2; a.Cin = 321; a.Tout = Th;
        a.LB = Th + 2; a.sB = 1; a.pad = 0; a.TmaxB = Th + 1;
        a.L1 = 2 * Th; a.s1s = 2; a.MoutLd = 321;
        k_mma<3, false><<<g2, 256>>>(a);
    }
    // conv1 U/P: B = D/C dense, pad 3
    {
        GA a{};
        for (int n = 0; n < cnt; n++) {
            a.z[2*n]   = {W1(nd[n].wi, 2), DQ[n], B1(nd[n].wi, 2), nullptr, YA[n], 0, 0, 0};
            a.z[2*n+1] = {W1(nd[n].wi, 3), CQ[n], B1(nd[n].wi, 3), nullptr, YB[n], 0, 0, 0};
        }
        a.Mrows = 321; a.Kdim = 1605; a.Kpad = KP1; a.Cin = 321; a.Tout = Th + 2;
        a.LB = Th; a.sB = 1; a.pad = 3; a.TmaxB = Th - 1;
        a.L1 = 0; a.s1s = 0; a.MoutLd = 321;
        k_mma<5, false><<<g1, 256>>>(a);
    }
    // conv2 U/P: EU = C + tanh (mode 2), OU = D - tanh (mode 3)
    {
        GA a{};
        for (int n = 0; n < cnt; n++) {
            a.z[2*n]   = {W2(nd[n].wi, 2), YA[n], B2(nd[n].wi, 2), CQ[n], nd[n].EU, 0, 0, 2};
            a.z[2*n+1] = {W2(nd[n].wi, 3), YB[n], B2(nd[n].wi, 3), DQ[n], nd[n].OU, 0, 0, 3};
        }
        a.Mrows = 321; a.Kdim = 963; a.Kpad = KP2; a.Cin = 321; a.Tout = Th;
        a.LB = Th + 2; a.sB = 1; a.pad = 0; a.TmaxB = Th + 1;
        a.L1 = Th; a.s1s = 1; a.MoutLd = 321;
        k_mma<3, false><<<g2, 256>>>(a);
    }
}

extern "C" void kernel_launch(void* const* d_in, const int* in_sizes, int n_in,
                              void* d_out, int out_size)
{
    float* pool = nullptr;
    cudaGetSymbolAddress((void**)&pool, g_pool);

    const float* x     = (const float*)d_in[0];
    const float* tw1   = (const float*)d_in[1];
    const float* tb1   = (const float*)d_in[2];
    const float* tw2   = (const float*)d_in[3];
    const float* tb2   = (const float*)d_in[4];
    const float* c1w   = (const float*)d_in[5];
    const float* c1b   = (const float*)d_in[6];
    const float* g1wih = (const float*)d_in[7];
    const float* g1whh = (const float*)d_in[8];
    const float* g1bih = (const float*)d_in[9];
    const float* g1bhh = (const float*)d_in[10];
    const float* gswih = (const float*)d_in[11];
    const float* gswhh = (const float*)d_in[12];
    const float* gsbih = (const float*)d_in[13];
    const float* gsbhh = (const float*)d_in[14];
    const float* linw  = (const float*)d_in[15];
    const float* linb  = (const float*)d_in[16];
    const float* hww   = (const float*)d_in[17];
    const float* hwb   = (const float*)d_in[18];

    float* Z0   = pool + O_Z0;
    float* XR   = pool + O_XR;
    float* EU0  = pool + O_EU0;  float* OU0  = pool + O_OU0;
    float* EU1A = pool + O_EU1A; float* OU1A = pool + O_OU1A;
    float* EU1B = pool + O_EU1B; float* OU1B = pool + O_OU1B;
    float* EU2[4]; float* OU2[4];
    for (int n = 0; n < 4; n++) {
        EU2[n] = pool + O_EU2 + (size_t)n * 24 * FU;
        OU2[n] = pool + O_OU2 + (size_t)n * 24 * FU;
    }
    float* R1 = pool + O_R1; float* R4 = pool + O_R4;
    float* R2 = pool + O_R2; float* R3 = pool + O_R3;
    float* CC  = pool + O_CC;
    float* GIb = pool + O_GI;
    float* H1  = pool + O_H1;
    float* HS  = pool + O_HS;
    uint32_t* WSpk = (uint32_t*)(pool + O_WSPK);
    uint32_t* WGpk = (uint32_t*)(pool + O_WGPK);

    // 0) weight conversion (split-bf16, padded)
    k_cvt_w<<<8192, 256>>>(tw1, (uint32_t*)(pool + O_W1PK), 28, 321, 384, 1605, KP1);
    k_cvt_w<<<8192, 256>>>(tw2, (uint32_t*)(pool + O_W2PK), 28, 321, 384, 963, KP2);
    k_cvt_w<<<1024, 256>>>(c1w, WSpk, 1, 128, 128, 1926, KPS);
    k_cvt_w<<<192, 256>>>(g1wih, WGpk, 1, 384, 384, 128, KPG);

    // 1) x -> BMT layout
    k_transpose_x<<<1024, 256>>>(x, Z0);

    // 2) SCINet tree, level-batched
    NodeIO n0[1] = {{0, Z0, EU0, OU0}};
    run_nodes(tb1, tb2, pool, n0, 1, 96);
    NodeIO n1[2] = {{1, EU0, EU1A, OU1A}, {4, OU0, EU1B, OU1B}};
    run_nodes(tb1, tb2, pool, n1, 2, 48);
    NodeIO n2[4] = {{2, EU1A, EU2[0], OU2[0]}, {3, OU1A, EU2[1], OU2[1]},
                    {5, EU1B, EU2[2], OU2[2]}, {6, OU1B, EU2[3], OU2[3]}};
    run_nodes(tb1, tb2, pool, n2, 4, 24);

    // zip-up-the-pants
    k_zip<<<512, 256>>>(EU2[0], OU2[0], R2, 24);
    k_zip<<<512, 256>>>(EU2[1], OU2[1], R3, 24);
    k_zip<<<1024, 256>>>(R2, R3, R1, 48);
    k_zip<<<512, 256>>>(EU2[2], OU2[2], R2, 24);
    k_zip<<<512, 256>>>(EU2[3], OU2[3], R3, 24);
    k_zip<<<1024, 256>>>(R2, R3, R4, 48);
    k_zip<<<1024, 256>>>(R1, R4, Z0, 96);     // res1 -> Z0

    // 3) xr = x + res1
    k_xr<<<1024, 256>>>(x, Z0, XR);

    // 4) conv stage (full-width Conv2d + relu): r = k*321 + m
    {
        GA a{};
        a.z[0] = {WSpk, XR, c1b, nullptr, CC, 0, 0, 4};
        a.Mrows = 128; a.Kdim = 1926; a.Kpad = KPS; a.Cin = 321; a.Tout = 187;
        a.LB = 192; a.sB = 1; a.pad = 0; a.TmaxB = 191;
        a.L1 = 0; a.s1s = 0; a.MoutLd = 128;
        k_mma<321, true><<<dim3(374, 1, 1), 256>>>(a);
    }

    // 5) GRU1 input projection (transposed store)
    {
        GA a{};
        a.z[0] = {WGpk, CC, g1bih, nullptr, GIb, 0, 0, 5};
        a.Mrows = 384; a.Kdim = 128; a.Kpad = KPG; a.Cin = 128; a.Tout = 187;
        a.LB = 187; a.sB = 1; a.pad = 0; a.TmaxB = 186;
        a.L1 = 0; a.s1s = 0; a.MoutLd = 384;
        k_mma<1, false><<<dim3(374, 3, 1), 256>>>(a);
    }

    // 6+7) GRU1 recurrence and skip GRU — independent, overlap on two streams
    {
        static cudaStream_t s2 = nullptr;
        static cudaEvent_t evFork = nullptr, evJoin = nullptr;
        if (!s2) {
            cudaStreamCreateWithFlags(&s2, cudaStreamNonBlocking);
            cudaEventCreateWithFlags(&evFork, cudaEventDisableTiming);
            cudaEventCreateWithFlags(&evJoin, cudaEventDisableTiming);
        }
        cudaEventRecord(evFork, 0);
        cudaStreamWaitEvent(s2, evFork, 0);
        k_gru1<<<128, 384>>>(GIb, g1whh, g1bhh, H1);
        k_skipgru<<<48, 128, 0, s2>>>(CC, gswih, gswhh, gsbih, gsbhh, HS);
        cudaEventRecord(evJoin, s2);
        cudaStreamWaitEvent(0, evJoin, 0);
    }

    // 8) head
    k_final<<<(82176 + 255) / 256, 256>>>(H1, HS, linw, linb, hww, hwb, XR,
                                          (float*)d_out);
}